// round 4
// baseline (speedup 1.0000x reference)
#include <cuda_runtime.h>
#include <math.h>
#include <stddef.h>
#include <stdint.h>

#define L_   2
#define D_   1024
#define H_   16
#define HD_  64
#define DFF_ 4096
#define V_   32000
#define B_   2
#define S_   1024
#define N_   (B_*S_)   // 2048 tokens

// ---------------- device scratch (static, no allocations) ----------------
__device__ float g_embm[(size_t)V_*D_];
__device__ float g_WqkvT[(size_t)L_*3*D_*D_];   // [l][3D][D]
__device__ float g_WoT [(size_t)L_*D_*D_];      // [l][D][D]
__device__ float g_W1T [(size_t)L_*DFF_*D_];    // [l][DFF][D]
__device__ float g_W2T [(size_t)L_*D_*DFF_];    // [l][D][DFF]
__device__ float g_g1  [L_*D_];
__device__ float g_g2  [L_*D_];
__device__ float g_gfm [D_];
__device__ float g_x   [(size_t)N_*D_];
__device__ float g_a   [(size_t)N_*D_];
__device__ float g_qkv [(size_t)N_*3*D_];
__device__ float g_att [(size_t)B_*H_*S_*S_];
__device__ float g_o   [(size_t)N_*D_];
__device__ float g_ff  [(size_t)N_*DFF_];
__device__ float g_logits[(size_t)N_*V_];
__device__ float g_nll [N_];

// ---------------- helpers ----------------
__device__ __forceinline__ float warp_sum(float v){
    #pragma unroll
    for (int o=16;o;o>>=1) v += __shfl_down_sync(0xffffffffu, v, o);
    return v;
}
__device__ __forceinline__ float warp_max(float v){
    #pragma unroll
    for (int o=16;o;o>>=1) v = fmaxf(v, __shfl_down_sync(0xffffffffu, v, o));
    return v;
}

// blockDim.x must be 256
template<bool MAXRED>
__device__ __forceinline__ float block_reduce(float v){
    __shared__ float sh[8];
    int tid = threadIdx.x;
    v = MAXRED ? warp_max(v) : warp_sum(v);
    __syncthreads();
    if ((tid & 31) == 0) sh[tid>>5] = v;
    __syncthreads();
    if (tid < 32){
        float a = (tid < 8) ? sh[tid] : (MAXRED ? -3.402823e38f : 0.f);
        a = MAXRED ? warp_max(a) : warp_sum(a);
        if (tid == 0) sh[0] = a;
    }
    __syncthreads();
    return sh[0];
}

__device__ __forceinline__ float gelu_f(float x){
    float x3 = x*x*x;
    return 0.5f*x*(1.f + tanhf(0.7978845608028654f*(x + 0.044715f*x3)));
}

// pack two floats to bf16x2 (lo = first/lower-k element)
__device__ __forceinline__ uint32_t pk_bf16x2(float lo, float hi){
    uint32_t r;
    asm("cvt.rn.bf16x2.f32 %0, %1, %2;" : "=r"(r) : "f"(hi), "f"(lo));
    return r;
}

// ---------------- merge: out = base + l0*delta0 + l1*delta1 ----------------
__global__ void merge_kernel(const float* __restrict__ base,
                             const float* __restrict__ delta,
                             const float* __restrict__ lam,
                             float* __restrict__ out, size_t n){
    size_t n4 = n >> 2;
    float l0 = lam[0], l1 = lam[1];
    const float4* b4 = (const float4*)base;
    const float4* d0 = (const float4*)delta;
    const float4* d1 = (const float4*)(delta + n);
    float4* o4 = (float4*)out;
    for (size_t i = (size_t)blockIdx.x*blockDim.x + threadIdx.x; i < n4;
         i += (size_t)gridDim.x*blockDim.x){
        float4 b = b4[i], x0 = d0[i], x1 = d1[i], r;
        r.x = b.x + l0*x0.x + l1*x1.x;
        r.y = b.y + l0*x0.y + l1*x1.y;
        r.z = b.z + l0*x0.z + l1*x1.z;
        r.w = b.w + l0*x0.w + l1*x1.w;
        o4[i] = r;
    }
}

// ------------- transpose-merge: out[z][n][k] = merged(base[z][k][n]) -------
// grid: (Nw/32, K/32, L), block (32, 8). tstride = L*K*Nw (elements per t-slice)
__global__ void tmerge_kernel(const float* __restrict__ base,
                              const float* __restrict__ delta,
                              const float* __restrict__ lam,
                              float* __restrict__ out,
                              int K, int Nw, size_t tstride){
    __shared__ float tile[32][33];
    int z = blockIdx.z;
    size_t mo = (size_t)z*K*Nw;
    float l0 = lam[0], l1 = lam[1];
    int n0 = blockIdx.x*32, k0 = blockIdx.y*32;
    #pragma unroll
    for (int j = 0; j < 32; j += 8){
        int k = k0 + threadIdx.y + j;
        int nn = n0 + threadIdx.x;
        size_t idx = mo + (size_t)k*Nw + nn;
        tile[threadIdx.y + j][threadIdx.x] =
            base[idx] + l0*delta[idx] + l1*delta[tstride + idx];
    }
    __syncthreads();
    #pragma unroll
    for (int j = 0; j < 32; j += 8){
        int nn = n0 + threadIdx.y + j;
        int k = k0 + threadIdx.x;
        out[mo + (size_t)nn*K + k] = tile[threadIdx.x][threadIdx.y + j];
    }
}

// ---------------- gather: x[t] = embm[ids[t]] ----------------
__global__ void gather_kernel(const int* __restrict__ ids,
                              const float* __restrict__ embm,
                              float* __restrict__ x){
    int t = blockIdx.x;
    int id = ids[t];
    const float4* src = (const float4*)(embm + (size_t)id*D_);
    float4* dst = (float4*)(x + (size_t)t*D_);
    for (int d = threadIdx.x; d < D_/4; d += blockDim.x) dst[d] = src[d];
}

// ---------------- layernorm ----------------
__global__ void ln_kernel(const float* __restrict__ x,
                          const float* __restrict__ g,
                          float* __restrict__ out){
    int t = blockIdx.x;
    int tid = threadIdx.x;
    const float* xr = x + (size_t)t*D_;
    float s = 0.f, ss = 0.f;
    for (int d = tid; d < D_; d += 256){ float v = xr[d]; s += v; ss = fmaf(v, v, ss); }
    float tots = block_reduce<false>(s);
    float totss = block_reduce<false>(ss);
    float mu = tots * (1.f/D_);
    float var = totss * (1.f/D_) - mu*mu;
    float inv = rsqrtf(var + 1e-5f);
    float* orow = out + (size_t)t*D_;
    for (int d = tid; d < D_; d += 256) orow[d] = (xr[d]-mu)*inv*g[d];
}

// ================= bf16 tensor-core GEMM (NT only) =================
// C(MxN) = [Res +] [gelu] ( A(MxK) @ Bt(NxK)^T ), fp32 in/out, bf16 mma inside.
// Block 256 thr, tile 128x128, BK=32. Warp tile 32x64 (4x2 warp grid).
// mma.sync.m16n8k16.bf16. Requires M%128==0, N%128==0, K%32==0.
// grid: (M/128, N/128)  -- x = M-block (fast) so co-resident CTAs share B in L2.
#define WS 18   // uint32 words per 32-k row (16 data + 2 pad)

template<int ACT, int RES>
__global__ void __launch_bounds__(256) bf16_gemm(int M, int N, int K,
                        const float* __restrict__ A,
                        const float* __restrict__ Bt,
                        const float* __restrict__ Res,
                        float* __restrict__ C){
    __shared__ uint32_t As[128*WS];
    __shared__ uint32_t Bs[128*WS];

    const int tid  = threadIdx.x;
    const int lane = tid & 31;
    const int warp = tid >> 5;
    const int g    = lane >> 2;     // 0..7
    const int t    = lane & 3;      // 0..3
    const int wm   = warp >> 1;     // 0..3
    const int wn   = warp & 1;      // 0..1
    const int row0 = blockIdx.x * 128;
    const int col0 = blockIdx.y * 128;

    float c[2][8][4];
    #pragma unroll
    for (int i=0;i<2;i++)
        #pragma unroll
        for (int j=0;j<8;j++)
            #pragma unroll
            for (int k=0;k<4;k++) c[i][j][k]=0.f;

    // gmem staging: each thread covers one row-half: 16 consecutive k (4 float4)
    const int lrow = tid >> 1;            // 0..127
    const int lk   = (tid & 1) * 16;      // 0 or 16
    const float* Ap = A  + (size_t)(row0 + lrow)*K + lk;
    const float* Bp = Bt + (size_t)(col0 + lrow)*K + lk;
    const int wb = lrow*WS + (tid & 1)*8; // smem word base

    float4 ra[4], rb[4];
    #pragma unroll
    for (int j = 0; j < 4; j++){
        ra[j] = *(const float4*)(Ap + 4*j);
        rb[j] = *(const float4*)(Bp + 4*j);
    }

    const int KT = K >> 5;
    for (int kt = 0; kt < KT; kt++){
        // ---- convert + store staged tile ----
        #pragma unroll
        for (int j = 0; j < 4; j++){
            uint2 va, vb;
            va.x = pk_bf16x2(ra[j].x, ra[j].y);
            va.y = pk_bf16x2(ra[j].z, ra[j].w);
            vb.x = pk_bf16x2(rb[j].x, rb[j].y);
            vb.y = pk_bf16x2(rb[j].z, rb[j].w);
            *(uint2*)&As[wb + 2*j] = va;
            *(uint2*)&Bs[wb + 2*j] = vb;
        }
        __syncthreads();

        // ---- prefetch next tile ----
        if (kt + 1 < KT){
            const float* Ap2 = Ap + (kt + 1)*32;
            const float* Bp2 = Bp + (kt + 1)*32;
            #pragma unroll
            for (int j = 0; j < 4; j++){
                ra[j] = *(const float4*)(Ap2 + 4*j);
                rb[j] = *(const float4*)(Bp2 + 4*j);
            }
        }

        // ---- compute: 2 x k16 sub-steps ----
        #pragma unroll
        for (int ks = 0; ks < 2; ks++){
            const int kw = ks * 8;
            unsigned af[2][4];
            unsigned bf[8][2];
            #pragma unroll
            for (int mt = 0; mt < 2; mt++){
                int base = (wm*32 + mt*16 + g)*WS + kw + t;
                af[mt][0] = As[base];
                af[mt][1] = As[base + 8*WS];
                af[mt][2] = As[base + 4];
                af[mt][3] = As[base + 8*WS + 4];
            }
            #pragma unroll
            for (int nt = 0; nt < 8; nt++){
                int nb = (wn*64 + nt*8 + g)*WS + kw + t;
                bf[nt][0] = Bs[nb];
                bf[nt][1] = Bs[nb + 4];
            }
            #pragma unroll
            for (int mt = 0; mt < 2; mt++)
                #pragma unroll
                for (int nt = 0; nt < 8; nt++){
                    asm volatile(
                        "mma.sync.aligned.m16n8k16.row.col.f32.bf16.bf16.f32 "
                        "{%0,%1,%2,%3}, {%4,%5,%6,%7}, {%8,%9}, {%0,%1,%2,%3};\n"
                        : "+f"(c[mt][nt][0]), "+f"(c[mt][nt][1]),
                          "+f"(c[mt][nt][2]), "+f"(c[mt][nt][3])
                        : "r"(af[mt][0]), "r"(af[mt][1]), "r"(af[mt][2]), "r"(af[mt][3]),
                          "r"(bf[nt][0]), "r"(bf[nt][1]));
                }
        }
        __syncthreads();
    }

    // ---- epilogue ----
    #pragma unroll
    for (int mt = 0; mt < 2; mt++){
        int r0 = row0 + wm*32 + mt*16 + g;
        #pragma unroll
        for (int nt = 0; nt < 8; nt++){
            int cc = col0 + wn*64 + nt*8 + 2*t;
            float v0 = c[mt][nt][0], v1 = c[mt][nt][1];
            float v2 = c[mt][nt][2], v3 = c[mt][nt][3];
            if (RES){
                v0 += Res[(size_t)r0*N + cc];
                v1 += Res[(size_t)r0*N + cc + 1];
                v2 += Res[(size_t)(r0+8)*N + cc];
                v3 += Res[(size_t)(r0+8)*N + cc + 1];
            }
            if (ACT){
                v0 = gelu_f(v0); v1 = gelu_f(v1);
                v2 = gelu_f(v2); v3 = gelu_f(v3);
            }
            C[(size_t)r0*N + cc]         = v0;
            C[(size_t)r0*N + cc + 1]     = v1;
            C[(size_t)(r0+8)*N + cc]     = v2;
            C[(size_t)(r0+8)*N + cc + 1] = v3;
        }
    }
}

// ---------------- attention scores: att[q,k] = q·k / 8 ----------------
__global__ void attn_scores(const float* __restrict__ qkv, float* __restrict__ att){
    int k0 = blockIdx.x*64, q0 = blockIdx.y*64;
    if (k0 > q0) return;
    int bh = blockIdx.z;
    int b = bh >> 4, h = bh & 15;
    __shared__ float Qs[64][65];
    __shared__ float Ks[64][65];
    int tid = threadIdx.y*16 + threadIdx.x;
    for (int i = tid; i < 4096; i += 256){
        int r = i >> 6, d = i & 63;
        Qs[r][d] = qkv[(size_t)(b*S_ + q0 + r)*(3*D_) + h*HD_ + d];
        Ks[r][d] = qkv[(size_t)(b*S_ + k0 + r)*(3*D_) + D_ + h*HD_ + d];
    }
    __syncthreads();
    float acc[4][4] = {};
    #pragma unroll
    for (int d = 0; d < 64; d++){
        float a[4], bb[4];
        #pragma unroll
        for (int i = 0; i < 4; i++) a[i] = Qs[threadIdx.y*4+i][d];
        #pragma unroll
        for (int j = 0; j < 4; j++) bb[j] = Ks[threadIdx.x*4+j][d];
        #pragma unroll
        for (int i = 0; i < 4; i++)
            #pragma unroll
            for (int j = 0; j < 4; j++)
                acc[i][j] = fmaf(a[i], bb[j], acc[i][j]);
    }
    size_t base = (size_t)bh * S_ * S_;
    #pragma unroll
    for (int i = 0; i < 4; i++){
        int q = q0 + threadIdx.y*4 + i;
        #pragma unroll
        for (int j = 0; j < 4; j++){
            int k = k0 + threadIdx.x*4 + j;
            att[base + (size_t)q*S_ + k] = acc[i][j]*0.125f;
        }
    }
}

// ---------------- causal softmax ----------------
__global__ void softmax_kernel(float* __restrict__ att){
    int q = blockIdx.x;
    int bh = blockIdx.y;
    int tid = threadIdx.x;
    float* row = att + ((size_t)bh*S_ + q)*S_;
    int len = q + 1;
    float mx = -3.402823e38f;
    for (int k = tid; k < len; k += 256) mx = fmaxf(mx, row[k]);
    mx = block_reduce<true>(mx);
    float sum = 0.f;
    for (int k = tid; k < len; k += 256){
        float e = expf(row[k] - mx);
        row[k] = e;
        sum += e;
    }
    sum = block_reduce<false>(sum);
    float rinv = 1.f / sum;
    for (int k = tid; k < S_; k += 256)
        row[k] = (k < len) ? row[k]*rinv : 0.f;
}

// ---------------- o = att @ v ----------------
__global__ void attn_o(const float* __restrict__ att, const float* __restrict__ qkv,
                       float* __restrict__ o){
    int q0 = blockIdx.x*64;
    int bh = blockIdx.y;
    int b = bh >> 4, h = bh & 15;
    __shared__ float Ps[64][65];
    __shared__ float Vs[64][65];
    int tid = threadIdx.y*16 + threadIdx.x;
    float acc[4][4] = {};
    size_t abase = (size_t)bh*S_*S_;
    for (int k0 = 0; k0 <= q0; k0 += 64){
        for (int i = tid; i < 4096; i += 256){
            int r = i >> 6, c = i & 63;
            Ps[r][c] = att[abase + (size_t)(q0+r)*S_ + k0 + c];
            Vs[r][c] = qkv[(size_t)(b*S_ + k0 + r)*(3*D_) + 2*D_ + h*HD_ + c];
        }
        __syncthreads();
        #pragma unroll
        for (int kk = 0; kk < 64; kk++){
            float a[4], bb[4];
            #pragma unroll
            for (int i = 0; i < 4; i++) a[i] = Ps[threadIdx.y*4+i][kk];
            #pragma unroll
            for (int j = 0; j < 4; j++) bb[j] = Vs[kk][threadIdx.x*4+j];
            #pragma unroll
            for (int i = 0; i < 4; i++)
                #pragma unroll
                for (int j = 0; j < 4; j++)
                    acc[i][j] = fmaf(a[i], bb[j], acc[i][j]);
        }
        __syncthreads();
    }
    #pragma unroll
    for (int i = 0; i < 4; i++){
        int q = q0 + threadIdx.y*4 + i;
        #pragma unroll
        for (int j = 0; j < 4; j++){
            int d = threadIdx.x*4 + j;
            o[(size_t)(b*S_ + q)*D_ + h*HD_ + d] = acc[i][j];
        }
    }
}

// ---------------- per-token NLL: single-pass online logsumexp ------------
__global__ void nll_kernel(const int* __restrict__ labels,
                           const float* __restrict__ logits,
                           float* __restrict__ nll){
    int t = blockIdx.x;
    int tid = threadIdx.x;
    int b = t >> 10, s = t & (S_-1);
    if (s == S_-1){ if (tid == 0) nll[t] = 0.f; return; }
    const float* row = logits + (size_t)t*V_;
    float m = -3.402823e38f, sum = 0.f;
    for (int i = tid; i < V_; i += 256){
        float v = row[i];
        float nm = fmaxf(m, v);
        sum = sum*expf(m - nm) + expf(v - nm);
        m = nm;
    }
    float M = block_reduce<true>(m);
    sum *= expf(m - M);
    float S = block_reduce<false>(sum);
    if (tid == 0){
        int tgt = labels[b*S_ + s + 1];
        nll[t] = logf(S) + M - row[tgt];
    }
}

// ---------------- final mean ----------------
__global__ void final_reduce(const float* __restrict__ nll, float* __restrict__ out){
    float s = 0.f;
    for (int t = threadIdx.x; t < N_; t += 256)
        if ((t & (S_-1)) != S_-1) s += nll[t];
    s = block_reduce<false>(s);
    if (threadIdx.x == 0) out[0] = s * (1.f/(B_*(S_-1)));
}

// ---------------- host launch ----------------
static inline int mgrid(size_t n){
    size_t n4 = n >> 2;
    size_t b = (n4 + 255) / 256;
    return (int)b;
}

extern "C" void kernel_launch(void* const* d_in, const int* in_sizes, int n_in,
                              void* d_out, int out_size){
    const int*   ids    = (const int*)  d_in[0];
    const int*   labels = (const int*)  d_in[1];
    const float* lam    = (const float*)d_in[2];
    const float* emb    = (const float*)d_in[3];
    const float* Wqkv   = (const float*)d_in[4];
    const float* Wo     = (const float*)d_in[5];
    const float* W1     = (const float*)d_in[6];
    const float* W2     = (const float*)d_in[7];
    const float* g1     = (const float*)d_in[8];
    const float* g2     = (const float*)d_in[9];
    const float* gf     = (const float*)d_in[10];
    const float* d_emb  = (const float*)d_in[11];
    const float* d_Wqkv = (const float*)d_in[12];
    const float* d_Wo   = (const float*)d_in[13];
    const float* d_W1   = (const float*)d_in[14];
    const float* d_W2   = (const float*)d_in[15];
    const float* d_g1   = (const float*)d_in[16];
    const float* d_g2   = (const float*)d_in[17];
    const float* d_gf   = (const float*)d_in[18];

    float *p_embm, *p_WqkvT, *p_WoT, *p_W1T, *p_W2T, *p_g1, *p_g2, *p_gf;
    float *p_x, *p_a, *p_qkv, *p_att, *p_o, *p_ff, *p_logits, *p_nll;
    cudaGetSymbolAddress((void**)&p_embm,   g_embm);
    cudaGetSymbolAddress((void**)&p_WqkvT,  g_WqkvT);
    cudaGetSymbolAddress((void**)&p_WoT,    g_WoT);
    cudaGetSymbolAddress((void**)&p_W1T,    g_W1T);
    cudaGetSymbolAddress((void**)&p_W2T,    g_W2T);
    cudaGetSymbolAddress((void**)&p_g1,     g_g1);
    cudaGetSymbolAddress((void**)&p_g2,     g_g2);
    cudaGetSymbolAddress((void**)&p_gf,     g_gfm);
    cudaGetSymbolAddress((void**)&p_x,      g_x);
    cudaGetSymbolAddress((void**)&p_a,      g_a);
    cudaGetSymbolAddress((void**)&p_qkv,    g_qkv);
    cudaGetSymbolAddress((void**)&p_att,    g_att);
    cudaGetSymbolAddress((void**)&p_o,      g_o);
    cudaGetSymbolAddress((void**)&p_ff,     g_ff);
    cudaGetSymbolAddress((void**)&p_logits, g_logits);
    cudaGetSymbolAddress((void**)&p_nll,    g_nll);

    // ---- merge weights ----
    size_t n;
    dim3 t328(32, 8);
    n = (size_t)V_*D_;  merge_kernel<<<mgrid(n),256>>>(emb,  d_emb,  lam, p_embm, n);
    // transposed merges: out[z][n][k]
    tmerge_kernel<<<dim3(3*D_/32, D_/32, L_), t328>>>(Wqkv, d_Wqkv, lam, p_WqkvT,
                     D_, 3*D_, (size_t)L_*D_*3*D_);
    tmerge_kernel<<<dim3(D_/32, D_/32, L_), t328>>>(Wo, d_Wo, lam, p_WoT,
                     D_, D_, (size_t)L_*D_*D_);
    tmerge_kernel<<<dim3(DFF_/32, D_/32, L_), t328>>>(W1, d_W1, lam, p_W1T,
                     D_, DFF_, (size_t)L_*D_*DFF_);
    tmerge_kernel<<<dim3(D_/32, DFF_/32, L_), t328>>>(W2, d_W2, lam, p_W2T,
                     DFF_, D_, (size_t)L_*DFF_*D_);
    n = (size_t)L_*D_;  merge_kernel<<<mgrid(n),256>>>(g1, d_g1, lam, p_g1, n);
    n = (size_t)L_*D_;  merge_kernel<<<mgrid(n),256>>>(g2, d_g2, lam, p_g2, n);
    n = (size_t)D_;     merge_kernel<<<mgrid(n),256>>>(gf, d_gf, lam, p_gf, n);

    // ---- embed ----
    gather_kernel<<<N_, 256>>>(ids, p_embm, p_x);

    dim3 thr(16,16);
    for (int l = 0; l < L_; l++){
        // attn
        ln_kernel<<<N_,256>>>(p_x, p_g1 + l*D_, p_a);
        bf16_gemm<0,0><<<dim3(N_/128, 3*D_/128), 256>>>(N_, 3*D_, D_, p_a,
                         p_WqkvT + (size_t)l*3*D_*D_, nullptr, p_qkv);
        attn_scores<<<dim3(S_/64, S_/64, B_*H_), thr>>>(p_qkv, p_att);
        softmax_kernel<<<dim3(S_, B_*H_), 256>>>(p_att);
        attn_o<<<dim3(S_/64, B_*H_), thr>>>(p_att, p_qkv, p_o);
        bf16_gemm<0,1><<<dim3(N_/128, D_/128), 256>>>(N_, D_, D_, p_o,
                         p_WoT + (size_t)l*D_*D_, p_x, p_x);
        // ffn
        ln_kernel<<<N_,256>>>(p_x, p_g2 + l*D_, p_a);
        bf16_gemm<1,0><<<dim3(N_/128, DFF_/128), 256>>>(N_, DFF_, D_, p_a,
                         p_W1T + (size_t)l*DFF_*D_, nullptr, p_ff);
        bf16_gemm<0,1><<<dim3(N_/128, D_/128), 256>>>(N_, D_, DFF_, p_ff,
                         p_W2T + (size_t)l*D_*DFF_, p_x, p_x);
    }

    // ---- head ----
    ln_kernel<<<N_,256>>>(p_x, p_gf, p_a);
    bf16_gemm<0,0><<<dim3(N_/128, V_/128), 256>>>(N_, V_, D_, p_a, p_embm,
                     nullptr, p_logits);
    nll_kernel<<<N_,256>>>(labels, p_logits, p_nll);
    final_reduce<<<1,256>>>(p_nll, (float*)d_out);
}

// round 5
// speedup vs baseline: 1.7390x; 1.7390x over previous
#include <cuda_runtime.h>
#include <cuda_bf16.h>
#include <math.h>
#include <stddef.h>
#include <stdint.h>

#define L_   2
#define D_   1024
#define H_   16
#define HD_  64
#define DFF_ 4096
#define V_   32000
#define B_   2
#define S_   1024
#define N_   (B_*S_)   // 2048 tokens

typedef __nv_bfloat16 bf16;

// ---------------- device scratch (static, no allocations) ----------------
__device__ float g_embm[(size_t)V_*D_];          // fp32 for gather
__device__ bf16  g_embh[(size_t)V_*D_];          // bf16 for logits GEMM
__device__ bf16  g_WqkvT[(size_t)L_*3*D_*D_];    // [l][3D][D]
__device__ bf16  g_WoT [(size_t)L_*D_*D_];       // [l][D][D]
__device__ bf16  g_W1T [(size_t)L_*DFF_*D_];     // [l][DFF][D]
__device__ bf16  g_W2T [(size_t)L_*D_*DFF_];     // [l][D][DFF]
__device__ float g_g1  [L_*D_];
__device__ float g_g2  [L_*D_];
__device__ float g_gfm [D_];
__device__ float g_x   [(size_t)N_*D_];
__device__ bf16  g_a   [(size_t)N_*D_];          // LN output (bf16)
__device__ float g_qkv [(size_t)N_*3*D_];
__device__ float g_att [(size_t)B_*H_*S_*S_];
__device__ bf16  g_o   [(size_t)N_*D_];          // attn output (bf16)
__device__ bf16  g_ff  [(size_t)N_*DFF_];        // GELU output (bf16)
__device__ float g_logits[(size_t)N_*V_];
__device__ float g_nll [N_];

// ---------------- helpers ----------------
__device__ __forceinline__ float warp_sum(float v){
    #pragma unroll
    for (int o=16;o;o>>=1) v += __shfl_down_sync(0xffffffffu, v, o);
    return v;
}
__device__ __forceinline__ float warp_max(float v){
    #pragma unroll
    for (int o=16;o;o>>=1) v = fmaxf(v, __shfl_down_sync(0xffffffffu, v, o));
    return v;
}

// blockDim.x must be 256
template<bool MAXRED>
__device__ __forceinline__ float block_reduce(float v){
    __shared__ float sh[8];
    int tid = threadIdx.x;
    v = MAXRED ? warp_max(v) : warp_sum(v);
    __syncthreads();
    if ((tid & 31) == 0) sh[tid>>5] = v;
    __syncthreads();
    if (tid < 32){
        float a = (tid < 8) ? sh[tid] : (MAXRED ? -3.402823e38f : 0.f);
        a = MAXRED ? warp_max(a) : warp_sum(a);
        if (tid == 0) sh[0] = a;
    }
    __syncthreads();
    return sh[0];
}

__device__ __forceinline__ float gelu_f(float x){
    float x3 = x*x*x;
    return 0.5f*x*(1.f + tanhf(0.7978845608028654f*(x + 0.044715f*x3)));
}

__device__ __forceinline__ uint32_t sptr(const void* p){
    return (uint32_t)__cvta_generic_to_shared(p);
}

#define CP16(dst, src) \
    asm volatile("cp.async.cg.shared.global [%0], [%1], 16;\n" :: "r"(dst), "l"(src))
#define CP_COMMIT()  asm volatile("cp.async.commit_group;\n" ::)
#define CP_WAIT1()   asm volatile("cp.async.wait_group 1;\n" ::)

#define LDSM4(r0,r1,r2,r3,addr) \
    asm volatile("ldmatrix.sync.aligned.m8n8.x4.shared.b16 {%0,%1,%2,%3}, [%4];" \
                 : "=r"(r0), "=r"(r1), "=r"(r2), "=r"(r3) : "r"(addr))

// ---------------- merge (fp32 out): small gains ----------------
__global__ void merge_kernel(const float* __restrict__ base,
                             const float* __restrict__ delta,
                             const float* __restrict__ lam,
                             float* __restrict__ out, size_t n){
    size_t n4 = n >> 2;
    float l0 = lam[0], l1 = lam[1];
    const float4* b4 = (const float4*)base;
    const float4* d0 = (const float4*)delta;
    const float4* d1 = (const float4*)(delta + n);
    float4* o4 = (float4*)out;
    for (size_t i = (size_t)blockIdx.x*blockDim.x + threadIdx.x; i < n4;
         i += (size_t)gridDim.x*blockDim.x){
        float4 b = b4[i], x0 = d0[i], x1 = d1[i], r;
        r.x = b.x + l0*x0.x + l1*x1.x;
        r.y = b.y + l0*x0.y + l1*x1.y;
        r.z = b.z + l0*x0.z + l1*x1.z;
        r.w = b.w + l0*x0.w + l1*x1.w;
        o4[i] = r;
    }
}

// ---------------- emb merge: fp32 + bf16 outputs ----------------
__global__ void merge_emb_kernel(const float* __restrict__ base,
                                 const float* __restrict__ delta,
                                 const float* __restrict__ lam,
                                 float* __restrict__ outf,
                                 bf16* __restrict__ outh, size_t n){
    size_t n4 = n >> 2;
    float l0 = lam[0], l1 = lam[1];
    const float4* b4 = (const float4*)base;
    const float4* d0 = (const float4*)delta;
    const float4* d1 = (const float4*)(delta + n);
    float4* o4 = (float4*)outf;
    __nv_bfloat162* h2 = (__nv_bfloat162*)outh;
    for (size_t i = (size_t)blockIdx.x*blockDim.x + threadIdx.x; i < n4;
         i += (size_t)gridDim.x*blockDim.x){
        float4 b = b4[i], x0 = d0[i], x1 = d1[i], r;
        r.x = b.x + l0*x0.x + l1*x1.x;
        r.y = b.y + l0*x0.y + l1*x1.y;
        r.z = b.z + l0*x0.z + l1*x1.z;
        r.w = b.w + l0*x0.w + l1*x1.w;
        o4[i] = r;
        h2[2*i]   = __floats2bfloat162_rn(r.x, r.y);
        h2[2*i+1] = __floats2bfloat162_rn(r.z, r.w);
    }
}

// ------------- transpose-merge -> bf16: out[z][n][k] = merged(base[z][k][n])
__global__ void tmerge_kernel(const float* __restrict__ base,
                              const float* __restrict__ delta,
                              const float* __restrict__ lam,
                              bf16* __restrict__ out,
                              int K, int Nw, size_t tstride){
    __shared__ float tile[32][33];
    int z = blockIdx.z;
    size_t mo = (size_t)z*K*Nw;
    float l0 = lam[0], l1 = lam[1];
    int n0 = blockIdx.x*32, k0 = blockIdx.y*32;
    #pragma unroll
    for (int j = 0; j < 32; j += 8){
        int k = k0 + threadIdx.y + j;
        int nn = n0 + threadIdx.x;
        size_t idx = mo + (size_t)k*Nw + nn;
        tile[threadIdx.y + j][threadIdx.x] =
            base[idx] + l0*delta[idx] + l1*delta[tstride + idx];
    }
    __syncthreads();
    #pragma unroll
    for (int j = 0; j < 32; j += 8){
        int nn = n0 + threadIdx.y + j;
        int k = k0 + threadIdx.x;
        out[mo + (size_t)nn*K + k] = __float2bfloat16(tile[threadIdx.x][threadIdx.y + j]);
    }
}

// ---------------- gather: x[t] = embm[ids[t]] ----------------
__global__ void gather_kernel(const int* __restrict__ ids,
                              const float* __restrict__ embm,
                              float* __restrict__ x){
    int t = blockIdx.x;
    int id = ids[t];
    const float4* src = (const float4*)(embm + (size_t)id*D_);
    float4* dst = (float4*)(x + (size_t)t*D_);
    for (int d = threadIdx.x; d < D_/4; d += blockDim.x) dst[d] = src[d];
}

// ---------------- layernorm: fp32 in -> bf16 out ----------------
__global__ void ln_kernel(const float* __restrict__ x,
                          const float* __restrict__ g,
                          bf16* __restrict__ out){
    int t = blockIdx.x;
    int tid = threadIdx.x;
    const float* xr = x + (size_t)t*D_;
    float s = 0.f, ss = 0.f;
    for (int d = tid; d < D_; d += 256){ float v = xr[d]; s += v; ss = fmaf(v, v, ss); }
    float tots = block_reduce<false>(s);
    float totss = block_reduce<false>(ss);
    float mu = tots * (1.f/D_);
    float var = totss * (1.f/D_) - mu*mu;
    float inv = rsqrtf(var + 1e-5f);
    bf16* orow = out + (size_t)t*D_;
    for (int d = tid; d < D_; d += 256)
        orow[d] = __float2bfloat16((xr[d]-mu)*inv*g[d]);
}

// ================= bf16 tensor-core GEMM (NT, cp.async + ldmatrix) =======
// C(MxN) = [Res +] [gelu] ( A(MxK) @ Bt(NxK)^T ), A/Bt bf16, accum fp32.
// Block 256 thr, tile 128x128, BK=32, 2-stage cp.async pipeline.
// Warp tile 32x64 (4x2 warp grid), mma.sync.m16n8k16.bf16.
// grid: (M/128, N/128); x = M fastest so co-resident CTAs share B in L2.
#define PAD 40   // bf16 elements per k-row slot (80 B, 16B-aligned, ldsm conflict-free)

template<int ACT, int RES, int OUTBF>
__global__ void __launch_bounds__(256) hgemm(int M, int N, int K,
                        const bf16* __restrict__ A,
                        const bf16* __restrict__ Bt,
                        const float* __restrict__ Res,
                        void* __restrict__ Cout){
    __shared__ __align__(16) bf16 As[2][128*PAD];
    __shared__ __align__(16) bf16 Bs[2][128*PAD];

    const int tid  = threadIdx.x;
    const int lane = tid & 31;
    const int warp = tid >> 5;
    const int g    = lane >> 2;
    const int t    = lane & 3;
    const int wm   = warp >> 1;     // 0..3
    const int wn   = warp & 1;      // 0..1
    const int row0 = blockIdx.x * 128;
    const int col0 = blockIdx.y * 128;

    float c[2][8][4];
    #pragma unroll
    for (int i=0;i<2;i++)
        #pragma unroll
        for (int j=0;j<8;j++)
            #pragma unroll
            for (int k=0;k<4;k++) c[i][j][k]=0.f;

    // ---- cp.async staging indices ----
    const int r1 = tid >> 2;          // 0..63
    const int c8 = (tid & 3) * 8;     // bf16 offset 0,8,16,24 (16B chunks)
    const bf16* Ag0 = A  + (size_t)(row0 + r1)*K + c8;
    const bf16* Ag1 = A  + (size_t)(row0 + r1 + 64)*K + c8;
    const bf16* Bg0 = Bt + (size_t)(col0 + r1)*K + c8;
    const bf16* Bg1 = Bt + (size_t)(col0 + r1 + 64)*K + c8;
    const uint32_t sa0 = sptr(&As[0][r1*PAD + c8]);
    const uint32_t sa1 = sptr(&As[0][(r1+64)*PAD + c8]);
    const uint32_t sb0 = sptr(&Bs[0][r1*PAD + c8]);
    const uint32_t sb1 = sptr(&Bs[0][(r1+64)*PAD + c8]);
    const uint32_t SS = 128*PAD*2;    // stage stride in bytes

    // ---- ldmatrix base addresses ----
    // A tile mt: rows wm*32 + mt*16 + (lane&15), koff (lane>>4)*8
    uint32_t aAddr[2];
    #pragma unroll
    for (int mt = 0; mt < 2; mt++)
        aAddr[mt] = sptr(&As[0][(wm*32 + mt*16 + (lane & 15))*PAD + (lane >> 4)*8]);
    // B tile bt (n16): n = wn*64 + bt*16 + ((lane>>4)&1)*8 + (lane&7), koff ((lane>>3)&1)*8
    uint32_t bAddr[4];
    #pragma unroll
    for (int bt = 0; bt < 4; bt++)
        bAddr[bt] = sptr(&Bs[0][(wn*64 + bt*16 + ((lane>>4)&1)*8 + (lane&7))*PAD
                                + ((lane>>3)&1)*8]);

    // ---- prologue: stage 0 ----
    {
        CP16(sa0, Ag0); CP16(sa1, Ag1);
        CP16(sb0, Bg0); CP16(sb1, Bg1);
        CP_COMMIT();
    }

    const int KT = K >> 5;
    int s = 0;
    for (int kt = 0; kt < KT; kt++){
        if (kt + 1 < KT){
            const int ko = (kt + 1) << 5;
            const uint32_t so = (s ^ 1) * SS;
            CP16(sa0 + so, Ag0 + ko); CP16(sa1 + so, Ag1 + ko);
            CP16(sb0 + so, Bg0 + ko); CP16(sb1 + so, Bg1 + ko);
        }
        CP_COMMIT();
        CP_WAIT1();
        __syncthreads();

        const uint32_t sb = s * SS;
        #pragma unroll
        for (int ks = 0; ks < 2; ks++){
            const uint32_t kb = sb + ks*32;   // 16 bf16 = 32 bytes
            uint32_t a[2][4];
            #pragma unroll
            for (int mt = 0; mt < 2; mt++)
                LDSM4(a[mt][0], a[mt][1], a[mt][2], a[mt][3], aAddr[mt] + kb);
            uint32_t bb[4][4];
            #pragma unroll
            for (int bt = 0; bt < 4; bt++)
                LDSM4(bb[bt][0], bb[bt][1], bb[bt][2], bb[bt][3], bAddr[bt] + kb);
            #pragma unroll
            for (int mt = 0; mt < 2; mt++)
                #pragma unroll
                for (int nt = 0; nt < 8; nt++){
                    const int bt = nt >> 1, su = (nt & 1) * 2;
                    asm volatile(
                        "mma.sync.aligned.m16n8k16.row.col.f32.bf16.bf16.f32 "
                        "{%0,%1,%2,%3}, {%4,%5,%6,%7}, {%8,%9}, {%0,%1,%2,%3};\n"
                        : "+f"(c[mt][nt][0]), "+f"(c[mt][nt][1]),
                          "+f"(c[mt][nt][2]), "+f"(c[mt][nt][3])
                        : "r"(a[mt][0]), "r"(a[mt][1]), "r"(a[mt][2]), "r"(a[mt][3]),
                          "r"(bb[bt][su]), "r"(bb[bt][su+1]));
                }
        }
        __syncthreads();
        s ^= 1;
    }

    // ---- epilogue ----
    float* Cf = (float*)Cout;
    bf16*  Ch = (bf16*)Cout;
    #pragma unroll
    for (int mt = 0; mt < 2; mt++){
        int r0 = row0 + wm*32 + mt*16 + g;
        #pragma unroll
        for (int nt = 0; nt < 8; nt++){
            int cc = col0 + wn*64 + nt*8 + 2*t;
            float v0 = c[mt][nt][0], v1 = c[mt][nt][1];
            float v2 = c[mt][nt][2], v3 = c[mt][nt][3];
            if (RES){
                v0 += Res[(size_t)r0*N + cc];
                v1 += Res[(size_t)r0*N + cc + 1];
                v2 += Res[(size_t)(r0+8)*N + cc];
                v3 += Res[(size_t)(r0+8)*N + cc + 1];
            }
            if (ACT){
                v0 = gelu_f(v0); v1 = gelu_f(v1);
                v2 = gelu_f(v2); v3 = gelu_f(v3);
            }
            if (OUTBF){
                *(__nv_bfloat162*)&Ch[(size_t)r0*N + cc]     = __floats2bfloat162_rn(v0, v1);
                *(__nv_bfloat162*)&Ch[(size_t)(r0+8)*N + cc] = __floats2bfloat162_rn(v2, v3);
            } else {
                Cf[(size_t)r0*N + cc]         = v0;
                Cf[(size_t)r0*N + cc + 1]     = v1;
                Cf[(size_t)(r0+8)*N + cc]     = v2;
                Cf[(size_t)(r0+8)*N + cc + 1] = v3;
            }
        }
    }
}

// ---------------- attention scores: att[q,k] = q·k / 8 ----------------
__global__ void attn_scores(const float* __restrict__ qkv, float* __restrict__ att){
    int k0 = blockIdx.x*64, q0 = blockIdx.y*64;
    if (k0 > q0) return;
    int bh = blockIdx.z;
    int b = bh >> 4, h = bh & 15;
    __shared__ float Qs[64][65];
    __shared__ float Ks[64][65];
    int tid = threadIdx.y*16 + threadIdx.x;
    for (int i = tid; i < 4096; i += 256){
        int r = i >> 6, d = i & 63;
        Qs[r][d] = qkv[(size_t)(b*S_ + q0 + r)*(3*D_) + h*HD_ + d];
        Ks[r][d] = qkv[(size_t)(b*S_ + k0 + r)*(3*D_) + D_ + h*HD_ + d];
    }
    __syncthreads();
    float acc[4][4] = {};
    #pragma unroll
    for (int d = 0; d < 64; d++){
        float a[4], bb[4];
        #pragma unroll
        for (int i = 0; i < 4; i++) a[i] = Qs[threadIdx.y*4+i][d];
        #pragma unroll
        for (int j = 0; j < 4; j++) bb[j] = Ks[threadIdx.x*4+j][d];
        #pragma unroll
        for (int i = 0; i < 4; i++)
            #pragma unroll
            for (int j = 0; j < 4; j++)
                acc[i][j] = fmaf(a[i], bb[j], acc[i][j]);
    }
    size_t base = (size_t)bh * S_ * S_;
    #pragma unroll
    for (int i = 0; i < 4; i++){
        int q = q0 + threadIdx.y*4 + i;
        #pragma unroll
        for (int j = 0; j < 4; j++){
            int k = k0 + threadIdx.x*4 + j;
            att[base + (size_t)q*S_ + k] = acc[i][j]*0.125f;
        }
    }
}

// ---------------- causal softmax ----------------
__global__ void softmax_kernel(float* __restrict__ att){
    int q = blockIdx.x;
    int bh = blockIdx.y;
    int tid = threadIdx.x;
    float* row = att + ((size_t)bh*S_ + q)*S_;
    int len = q + 1;
    float mx = -3.402823e38f;
    for (int k = tid; k < len; k += 256) mx = fmaxf(mx, row[k]);
    mx = block_reduce<true>(mx);
    float sum = 0.f;
    for (int k = tid; k < len; k += 256){
        float e = expf(row[k] - mx);
        row[k] = e;
        sum += e;
    }
    sum = block_reduce<false>(sum);
    float rinv = 1.f / sum;
    for (int k = tid; k < S_; k += 256)
        row[k] = (k < len) ? row[k]*rinv : 0.f;
}

// ---------------- o = att @ v  (bf16 out) ----------------
__global__ void attn_o(const float* __restrict__ att, const float* __restrict__ qkv,
                       bf16* __restrict__ o){
    int q0 = blockIdx.x*64;
    int bh = blockIdx.y;
    int b = bh >> 4, h = bh & 15;
    __shared__ float Ps[64][65];
    __shared__ float Vs[64][65];
    int tid = threadIdx.y*16 + threadIdx.x;
    float acc[4][4] = {};
    size_t abase = (size_t)bh*S_*S_;
    for (int k0 = 0; k0 <= q0; k0 += 64){
        for (int i = tid; i < 4096; i += 256){
            int r = i >> 6, c = i & 63;
            Ps[r][c] = att[abase + (size_t)(q0+r)*S_ + k0 + c];
            Vs[r][c] = qkv[(size_t)(b*S_ + k0 + r)*(3*D_) + 2*D_ + h*HD_ + c];
        }
        __syncthreads();
        #pragma unroll
        for (int kk = 0; kk < 64; kk++){
            float a[4], bb[4];
            #pragma unroll
            for (int i = 0; i < 4; i++) a[i] = Ps[threadIdx.y*4+i][kk];
            #pragma unroll
            for (int j = 0; j < 4; j++) bb[j] = Vs[kk][threadIdx.x*4+j];
            #pragma unroll
            for (int i = 0; i < 4; i++)
                #pragma unroll
                for (int j = 0; j < 4; j++)
                    acc[i][j] = fmaf(a[i], bb[j], acc[i][j]);
        }
        __syncthreads();
    }
    #pragma unroll
    for (int i = 0; i < 4; i++){
        int q = q0 + threadIdx.y*4 + i;
        #pragma unroll
        for (int j = 0; j < 4; j++){
            int d = threadIdx.x*4 + j;
            o[(size_t)(b*S_ + q)*D_ + h*HD_ + d] = __float2bfloat16(acc[i][j]);
        }
    }
}

// ---------------- per-token NLL: single-pass online logsumexp ------------
__global__ void nll_kernel(const int* __restrict__ labels,
                           const float* __restrict__ logits,
                           float* __restrict__ nll){
    int t = blockIdx.x;
    int tid = threadIdx.x;
    int b = t >> 10, s = t & (S_-1);
    if (s == S_-1){ if (tid == 0) nll[t] = 0.f; return; }
    const float* row = logits + (size_t)t*V_;
    float m = -3.402823e38f, sum = 0.f;
    for (int i = tid; i < V_; i += 256){
        float v = row[i];
        float nm = fmaxf(m, v);
        sum = sum*expf(m - nm) + expf(v - nm);
        m = nm;
    }
    float M = block_reduce<true>(m);
    sum *= expf(m - M);
    float S = block_reduce<false>(sum);
    if (tid == 0){
        int tgt = labels[b*S_ + s + 1];
        nll[t] = logf(S) + M - row[tgt];
    }
}

// ---------------- final mean ----------------
__global__ void final_reduce(const float* __restrict__ nll, float* __restrict__ out){
    float s = 0.f;
    for (int t = threadIdx.x; t < N_; t += 256)
        if ((t & (S_-1)) != S_-1) s += nll[t];
    s = block_reduce<false>(s);
    if (threadIdx.x == 0) out[0] = s * (1.f/(B_*(S_-1)));
}

// ---------------- host launch ----------------
static inline int mgrid(size_t n){
    size_t n4 = n >> 2;
    size_t b = (n4 + 255) / 256;
    return (int)b;
}

extern "C" void kernel_launch(void* const* d_in, const int* in_sizes, int n_in,
                              void* d_out, int out_size){
    const int*   ids    = (const int*)  d_in[0];
    const int*   labels = (const int*)  d_in[1];
    const float* lam    = (const float*)d_in[2];
    const float* emb    = (const float*)d_in[3];
    const float* Wqkv   = (const float*)d_in[4];
    const float* Wo     = (const float*)d_in[5];
    const float* W1     = (const float*)d_in[6];
    const float* W2     = (const float*)d_in[7];
    const float* g1     = (const float*)d_in[8];
    const float* g2     = (const float*)d_in[9];
    const float* gf     = (const float*)d_in[10];
    const float* d_emb  = (const float*)d_in[11];
    const float* d_Wqkv = (const float*)d_in[12];
    const float* d_Wo   = (const float*)d_in[13];
    const float* d_W1   = (const float*)d_in[14];
    const float* d_W2   = (const float*)d_in[15];
    const float* d_g1   = (const float*)d_in[16];
    const float* d_g2   = (const float*)d_in[17];
    const float* d_gf   = (const float*)d_in[18];

    float *p_embm, *p_g1, *p_g2, *p_gf;
    bf16  *p_embh, *p_WqkvT, *p_WoT, *p_W1T, *p_W2T, *p_a, *p_o, *p_ff;
    float *p_x, *p_qkv, *p_att, *p_logits, *p_nll;
    cudaGetSymbolAddress((void**)&p_embm,   g_embm);
    cudaGetSymbolAddress((void**)&p_embh,   g_embh);
    cudaGetSymbolAddress((void**)&p_WqkvT,  g_WqkvT);
    cudaGetSymbolAddress((void**)&p_WoT,    g_WoT);
    cudaGetSymbolAddress((void**)&p_W1T,    g_W1T);
    cudaGetSymbolAddress((void**)&p_W2T,    g_W2T);
    cudaGetSymbolAddress((void**)&p_g1,     g_g1);
    cudaGetSymbolAddress((void**)&p_g2,     g_g2);
    cudaGetSymbolAddress((void**)&p_gf,     g_gfm);
    cudaGetSymbolAddress((void**)&p_x,      g_x);
    cudaGetSymbolAddress((void**)&p_a,      g_a);
    cudaGetSymbolAddress((void**)&p_qkv,    g_qkv);
    cudaGetSymbolAddress((void**)&p_att,    g_att);
    cudaGetSymbolAddress((void**)&p_o,      g_o);
    cudaGetSymbolAddress((void**)&p_ff,     g_ff);
    cudaGetSymbolAddress((void**)&p_logits, g_logits);
    cudaGetSymbolAddress((void**)&p_nll,    g_nll);

    // ---- merge weights ----
    size_t n;
    dim3 t328(32, 8);
    n = (size_t)V_*D_;
    merge_emb_kernel<<<mgrid(n),256>>>(emb, d_emb, lam, p_embm, p_embh, n);
    tmerge_kernel<<<dim3(3*D_/32, D_/32, L_), t328>>>(Wqkv, d_Wqkv, lam, p_WqkvT,
                     D_, 3*D_, (size_t)L_*D_*3*D_);
    tmerge_kernel<<<dim3(D_/32, D_/32, L_), t328>>>(Wo, d_Wo, lam, p_WoT,
                     D_, D_, (size_t)L_*D_*D_);
    tmerge_kernel<<<dim3(DFF_/32, D_/32, L_), t328>>>(W1, d_W1, lam, p_W1T,
                     D_, DFF_, (size_t)L_*D_*DFF_);
    tmerge_kernel<<<dim3(D_/32, DFF_/32, L_), t328>>>(W2, d_W2, lam, p_W2T,
                     DFF_, D_, (size_t)L_*DFF_*D_);
    n = (size_t)L_*D_;  merge_kernel<<<mgrid(n),256>>>(g1, d_g1, lam, p_g1, n);
    n = (size_t)L_*D_;  merge_kernel<<<mgrid(n),256>>>(g2, d_g2, lam, p_g2, n);
    n = (size_t)D_;     merge_kernel<<<mgrid(n),256>>>(gf, d_gf, lam, p_gf, n);

    // ---- embed ----
    gather_kernel<<<N_, 256>>>(ids, p_embm, p_x);

    dim3 thr(16,16);
    for (int l = 0; l < L_; l++){
        // attn
        ln_kernel<<<N_,256>>>(p_x, p_g1 + l*D_, p_a);
        hgemm<0,0,0><<<dim3(N_/128, 3*D_/128), 256>>>(N_, 3*D_, D_, p_a,
                         p_WqkvT + (size_t)l*3*D_*D_, nullptr, p_qkv);
        attn_scores<<<dim3(S_/64, S_/64, B_*H_), thr>>>(p_qkv, p_att);
        softmax_kernel<<<dim3(S_, B_*H_), 256>>>(p_att);
        attn_o<<<dim3(S_/64, B_*H_), thr>>>(p_att, p_qkv, p_o);
        hgemm<0,1,0><<<dim3(N_/128, D_/128), 256>>>(N_, D_, D_, p_o,
                         p_WoT + (size_t)l*D_*D_, p_x, p_x);
        // ffn
        ln_kernel<<<N_,256>>>(p_x, p_g2 + l*D_, p_a);
        hgemm<1,0,1><<<dim3(N_/128, DFF_/128), 256>>>(N_, DFF_, D_, p_a,
                         p_W1T + (size_t)l*DFF_*D_, nullptr, p_ff);
        hgemm<0,1,0><<<dim3(N_/128, D_/128), 256>>>(N_, D_, DFF_, p_ff,
                         p_W2T + (size_t)l*D_*DFF_, p_x, p_x);
    }

    // ---- head ----
    ln_kernel<<<N_,256>>>(p_x, p_gf, p_a);
    hgemm<0,0,0><<<dim3(N_/128, V_/128), 256>>>(N_, V_, D_, p_a, p_embh,
                     nullptr, p_logits);
    nll_kernel<<<N_,256>>>(labels, p_logits, p_nll);
    final_reduce<<<1,256>>>(p_nll, (float*)d_out);
}

// round 6
// speedup vs baseline: 2.5398x; 1.4605x over previous
#include <cuda_runtime.h>
#include <cuda_bf16.h>
#include <math.h>
#include <stddef.h>
#include <stdint.h>

#define L_   2
#define D_   1024
#define H_   16
#define HD_  64
#define DFF_ 4096
#define V_   32000
#define B_   2
#define S_   1024
#define N_   (B_*S_)   // 2048 tokens

typedef __nv_bfloat16 bf16;

// ---------------- device scratch (static, no allocations) ----------------
__device__ float g_embm[(size_t)V_*D_];          // fp32 for gather
__device__ bf16  g_embh[(size_t)V_*D_];          // bf16 for logits GEMM
__device__ bf16  g_WqkvT[(size_t)L_*3*D_*D_];    // [l][3D][D]
__device__ bf16  g_WoT [(size_t)L_*D_*D_];       // [l][D][D]
__device__ bf16  g_W1T [(size_t)L_*DFF_*D_];     // [l][DFF][D]
__device__ bf16  g_W2T [(size_t)L_*D_*DFF_];     // [l][D][DFF]
__device__ float g_g1  [L_*D_];
__device__ float g_g2  [L_*D_];
__device__ float g_gfm [D_];
__device__ float g_x   [(size_t)N_*D_];
__device__ bf16  g_a   [(size_t)N_*D_];          // LN output (bf16)
__device__ bf16  g_qkvh[(size_t)N_*3*D_];        // qkv (bf16)
__device__ bf16  g_o   [(size_t)N_*D_];          // attn output (bf16)
__device__ bf16  g_ff  [(size_t)N_*DFF_];        // GELU output (bf16)
__device__ float g_logits[(size_t)N_*V_];
__device__ float g_nll [N_];

// ---------------- helpers ----------------
__device__ __forceinline__ float warp_sum(float v){
    #pragma unroll
    for (int o=16;o;o>>=1) v += __shfl_down_sync(0xffffffffu, v, o);
    return v;
}
__device__ __forceinline__ float warp_max(float v){
    #pragma unroll
    for (int o=16;o;o>>=1) v = fmaxf(v, __shfl_down_sync(0xffffffffu, v, o));
    return v;
}

// blockDim.x must be 256
template<bool MAXRED>
__device__ __forceinline__ float block_reduce(float v){
    __shared__ float sh[8];
    int tid = threadIdx.x;
    v = MAXRED ? warp_max(v) : warp_sum(v);
    __syncthreads();
    if ((tid & 31) == 0) sh[tid>>5] = v;
    __syncthreads();
    if (tid < 32){
        float a = (tid < 8) ? sh[tid] : (MAXRED ? -3.402823e38f : 0.f);
        a = MAXRED ? warp_max(a) : warp_sum(a);
        if (tid == 0) sh[0] = a;
    }
    __syncthreads();
    return sh[0];
}

__device__ __forceinline__ float gelu_f(float x){
    float x3 = x*x*x;
    return 0.5f*x*(1.f + tanhf(0.7978845608028654f*(x + 0.044715f*x3)));
}

__device__ __forceinline__ uint32_t sptr(const void* p){
    return (uint32_t)__cvta_generic_to_shared(p);
}
__device__ __forceinline__ uint32_t pk2(float lo, float hi){
    uint32_t r;
    asm("cvt.rn.bf16x2.f32 %0, %1, %2;" : "=r"(r) : "f"(hi), "f"(lo));
    return r;
}

#define CP16(dst, src) \
    asm volatile("cp.async.cg.shared.global [%0], [%1], 16;\n" :: "r"(dst), "l"(src))
#define CP_COMMIT()  asm volatile("cp.async.commit_group;\n" ::)
#define CP_WAIT1()   asm volatile("cp.async.wait_group 1;\n" ::)
#define CP_WAIT0()   asm volatile("cp.async.wait_group 0;\n" ::)

#define LDSM4(r0,r1,r2,r3,addr) \
    asm volatile("ldmatrix.sync.aligned.m8n8.x4.shared.b16 {%0,%1,%2,%3}, [%4];" \
                 : "=r"(r0), "=r"(r1), "=r"(r2), "=r"(r3) : "r"(addr))
#define LDSM4T(r0,r1,r2,r3,addr) \
    asm volatile("ldmatrix.sync.aligned.m8n8.x4.trans.shared.b16 {%0,%1,%2,%3}, [%4];" \
                 : "=r"(r0), "=r"(r1), "=r"(r2), "=r"(r3) : "r"(addr))

#define MMA16816(c0,c1,c2,c3,a0,a1,a2,a3,b0,b1) \
    asm volatile( \
        "mma.sync.aligned.m16n8k16.row.col.f32.bf16.bf16.f32 " \
        "{%0,%1,%2,%3}, {%4,%5,%6,%7}, {%8,%9}, {%0,%1,%2,%3};\n" \
        : "+f"(c0), "+f"(c1), "+f"(c2), "+f"(c3) \
        : "r"(a0), "r"(a1), "r"(a2), "r"(a3), "r"(b0), "r"(b1))

// ---------------- merge (fp32 out) ----------------
__global__ void merge_kernel(const float* __restrict__ base,
                             const float* __restrict__ delta,
                             const float* __restrict__ lam,
                             float* __restrict__ out, size_t n){
    size_t n4 = n >> 2;
    float l0 = lam[0], l1 = lam[1];
    const float4* b4 = (const float4*)base;
    const float4* d0 = (const float4*)delta;
    const float4* d1 = (const float4*)(delta + n);
    float4* o4 = (float4*)out;
    for (size_t i = (size_t)blockIdx.x*blockDim.x + threadIdx.x; i < n4;
         i += (size_t)gridDim.x*blockDim.x){
        float4 b = b4[i], x0 = d0[i], x1 = d1[i], r;
        r.x = b.x + l0*x0.x + l1*x1.x;
        r.y = b.y + l0*x0.y + l1*x1.y;
        r.z = b.z + l0*x0.z + l1*x1.z;
        r.w = b.w + l0*x0.w + l1*x1.w;
        o4[i] = r;
    }
}

// ---------------- emb merge: fp32 + bf16 outputs ----------------
__global__ void merge_emb_kernel(const float* __restrict__ base,
                                 const float* __restrict__ delta,
                                 const float* __restrict__ lam,
                                 float* __restrict__ outf,
                                 bf16* __restrict__ outh, size_t n){
    size_t n4 = n >> 2;
    float l0 = lam[0], l1 = lam[1];
    const float4* b4 = (const float4*)base;
    const float4* d0 = (const float4*)delta;
    const float4* d1 = (const float4*)(delta + n);
    float4* o4 = (float4*)outf;
    __nv_bfloat162* h2 = (__nv_bfloat162*)outh;
    for (size_t i = (size_t)blockIdx.x*blockDim.x + threadIdx.x; i < n4;
         i += (size_t)gridDim.x*blockDim.x){
        float4 b = b4[i], x0 = d0[i], x1 = d1[i], r;
        r.x = b.x + l0*x0.x + l1*x1.x;
        r.y = b.y + l0*x0.y + l1*x1.y;
        r.z = b.z + l0*x0.z + l1*x1.z;
        r.w = b.w + l0*x0.w + l1*x1.w;
        o4[i] = r;
        h2[2*i]   = __floats2bfloat162_rn(r.x, r.y);
        h2[2*i+1] = __floats2bfloat162_rn(r.z, r.w);
    }
}

// ------------- transpose-merge -> bf16 ----------------
__global__ void tmerge_kernel(const float* __restrict__ base,
                              const float* __restrict__ delta,
                              const float* __restrict__ lam,
                              bf16* __restrict__ out,
                              int K, int Nw, size_t tstride){
    __shared__ float tile[32][33];
    int z = blockIdx.z;
    size_t mo = (size_t)z*K*Nw;
    float l0 = lam[0], l1 = lam[1];
    int n0 = blockIdx.x*32, k0 = blockIdx.y*32;
    #pragma unroll
    for (int j = 0; j < 32; j += 8){
        int k = k0 + threadIdx.y + j;
        int nn = n0 + threadIdx.x;
        size_t idx = mo + (size_t)k*Nw + nn;
        tile[threadIdx.y + j][threadIdx.x] =
            base[idx] + l0*delta[idx] + l1*delta[tstride + idx];
    }
    __syncthreads();
    #pragma unroll
    for (int j = 0; j < 32; j += 8){
        int nn = n0 + threadIdx.y + j;
        int k = k0 + threadIdx.x;
        out[mo + (size_t)nn*K + k] = __float2bfloat16(tile[threadIdx.x][threadIdx.y + j]);
    }
}

// ---------------- gather ----------------
__global__ void gather_kernel(const int* __restrict__ ids,
                              const float* __restrict__ embm,
                              float* __restrict__ x){
    int t = blockIdx.x;
    int id = ids[t];
    const float4* src = (const float4*)(embm + (size_t)id*D_);
    float4* dst = (float4*)(x + (size_t)t*D_);
    for (int d = threadIdx.x; d < D_/4; d += blockDim.x) dst[d] = src[d];
}

// ---------------- layernorm: fp32 in -> bf16 out ----------------
__global__ void ln_kernel(const float* __restrict__ x,
                          const float* __restrict__ g,
                          bf16* __restrict__ out){
    int t = blockIdx.x;
    int tid = threadIdx.x;
    const float* xr = x + (size_t)t*D_;
    float s = 0.f, ss = 0.f;
    for (int d = tid; d < D_; d += 256){ float v = xr[d]; s += v; ss = fmaf(v, v, ss); }
    float tots = block_reduce<false>(s);
    float totss = block_reduce<false>(ss);
    float mu = tots * (1.f/D_);
    float var = totss * (1.f/D_) - mu*mu;
    float inv = rsqrtf(var + 1e-5f);
    bf16* orow = out + (size_t)t*D_;
    for (int d = tid; d < D_; d += 256)
        orow[d] = __float2bfloat16((xr[d]-mu)*inv*g[d]);
}

// ================= bf16 GEMM (NT, cp.async + ldmatrix) ====================
#define PAD 40

template<int ACT, int RES, int OUTBF>
__global__ void __launch_bounds__(256) hgemm(int M, int N, int K,
                        const bf16* __restrict__ A,
                        const bf16* __restrict__ Bt,
                        const float* __restrict__ Res,
                        void* __restrict__ Cout){
    __shared__ __align__(16) bf16 As[2][128*PAD];
    __shared__ __align__(16) bf16 Bs[2][128*PAD];

    const int tid  = threadIdx.x;
    const int lane = tid & 31;
    const int warp = tid >> 5;
    const int g    = lane >> 2;
    const int t    = lane & 3;
    const int wm   = warp >> 1;
    const int wn   = warp & 1;
    const int row0 = blockIdx.x * 128;
    const int col0 = blockIdx.y * 128;

    float c[2][8][4];
    #pragma unroll
    for (int i=0;i<2;i++)
        #pragma unroll
        for (int j=0;j<8;j++)
            #pragma unroll
            for (int k=0;k<4;k++) c[i][j][k]=0.f;

    const int r1 = tid >> 2;
    const int c8 = (tid & 3) * 8;
    const bf16* Ag0 = A  + (size_t)(row0 + r1)*K + c8;
    const bf16* Ag1 = A  + (size_t)(row0 + r1 + 64)*K + c8;
    const bf16* Bg0 = Bt + (size_t)(col0 + r1)*K + c8;
    const bf16* Bg1 = Bt + (size_t)(col0 + r1 + 64)*K + c8;
    const uint32_t sa0 = sptr(&As[0][r1*PAD + c8]);
    const uint32_t sa1 = sptr(&As[0][(r1+64)*PAD + c8]);
    const uint32_t sb0 = sptr(&Bs[0][r1*PAD + c8]);
    const uint32_t sb1 = sptr(&Bs[0][(r1+64)*PAD + c8]);
    const uint32_t SS = 128*PAD*2;

    uint32_t aAddr[2];
    #pragma unroll
    for (int mt = 0; mt < 2; mt++)
        aAddr[mt] = sptr(&As[0][(wm*32 + mt*16 + (lane & 15))*PAD + (lane >> 4)*8]);
    uint32_t bAddr[4];
    #pragma unroll
    for (int bt = 0; bt < 4; bt++)
        bAddr[bt] = sptr(&Bs[0][(wn*64 + bt*16 + ((lane>>4)&1)*8 + (lane&7))*PAD
                                + ((lane>>3)&1)*8]);

    {
        CP16(sa0, Ag0); CP16(sa1, Ag1);
        CP16(sb0, Bg0); CP16(sb1, Bg1);
        CP_COMMIT();
    }

    const int KT = K >> 5;
    int s = 0;
    for (int kt = 0; kt < KT; kt++){
        if (kt + 1 < KT){
            const int ko = (kt + 1) << 5;
            const uint32_t so = (s ^ 1) * SS;
            CP16(sa0 + so, Ag0 + ko); CP16(sa1 + so, Ag1 + ko);
            CP16(sb0 + so, Bg0 + ko); CP16(sb1 + so, Bg1 + ko);
        }
        CP_COMMIT();
        CP_WAIT1();
        __syncthreads();

        const uint32_t sb = s * SS;
        #pragma unroll
        for (int ks = 0; ks < 2; ks++){
            const uint32_t kb = sb + ks*32;
            uint32_t a[2][4];
            #pragma unroll
            for (int mt = 0; mt < 2; mt++)
                LDSM4(a[mt][0], a[mt][1], a[mt][2], a[mt][3], aAddr[mt] + kb);
            uint32_t bb[4][4];
            #pragma unroll
            for (int bt = 0; bt < 4; bt++)
                LDSM4(bb[bt][0], bb[bt][1], bb[bt][2], bb[bt][3], bAddr[bt] + kb);
            #pragma unroll
            for (int mt = 0; mt < 2; mt++)
                #pragma unroll
                for (int nt = 0; nt < 8; nt++){
                    const int bt = nt >> 1, su = (nt & 1) * 2;
                    MMA16816(c[mt][nt][0], c[mt][nt][1], c[mt][nt][2], c[mt][nt][3],
                             a[mt][0], a[mt][1], a[mt][2], a[mt][3],
                             bb[bt][su], bb[bt][su+1]);
                }
        }
        __syncthreads();
        s ^= 1;
    }

    float* Cf = (float*)Cout;
    bf16*  Ch = (bf16*)Cout;
    #pragma unroll
    for (int mt = 0; mt < 2; mt++){
        int r0 = row0 + wm*32 + mt*16 + g;
        #pragma unroll
        for (int nt = 0; nt < 8; nt++){
            int cc = col0 + wn*64 + nt*8 + 2*t;
            float v0 = c[mt][nt][0], v1 = c[mt][nt][1];
            float v2 = c[mt][nt][2], v3 = c[mt][nt][3];
            if (RES){
                v0 += Res[(size_t)r0*N + cc];
                v1 += Res[(size_t)r0*N + cc + 1];
                v2 += Res[(size_t)(r0+8)*N + cc];
                v3 += Res[(size_t)(r0+8)*N + cc + 1];
            }
            if (ACT){
                v0 = gelu_f(v0); v1 = gelu_f(v1);
                v2 = gelu_f(v2); v3 = gelu_f(v3);
            }
            if (OUTBF){
                *(__nv_bfloat162*)&Ch[(size_t)r0*N + cc]     = __floats2bfloat162_rn(v0, v1);
                *(__nv_bfloat162*)&Ch[(size_t)(r0+8)*N + cc] = __floats2bfloat162_rn(v2, v3);
            } else {
                Cf[(size_t)r0*N + cc]         = v0;
                Cf[(size_t)r0*N + cc + 1]     = v1;
                Cf[(size_t)(r0+8)*N + cc]     = v2;
                Cf[(size_t)(r0+8)*N + cc + 1] = v3;
            }
        }
    }
}

// ================= fused flash attention ==================================
// grid (S/128, B*H), block 256 (8 warps). Q tile 128 rows; K/V tiles 64 keys.
// qkv bf16 token-major [t][3D]; out bf16 [t][D] at head offset.
#define QPAD 72   // bf16 per row (144 B): ldmatrix conflict-free for HD=64

__global__ void __launch_bounds__(256) flash_attn(const bf16* __restrict__ qkv,
                                                  bf16* __restrict__ out){
    __shared__ __align__(16) bf16 Qs[128*QPAD];
    __shared__ __align__(16) bf16 Ks[2][64*QPAD];
    __shared__ __align__(16) bf16 Vs[2][64*QPAD];

    const int tid  = threadIdx.x;
    const int lane = tid & 31;
    const int warp = tid >> 5;
    const int g    = lane >> 2;
    const int t    = lane & 3;
    const int qt   = blockIdx.x;
    const int bh   = blockIdx.y;
    const int b    = bh >> 4, h = bh & 15;
    const int q0   = qt * 128;

    const size_t tok0 = (size_t)b * S_;
    const bf16* Qg = qkv + (tok0 + q0)*(3*D_) + h*HD_;
    const bf16* Kg = qkv + tok0*(3*D_) + D_   + h*HD_;
    const bf16* Vg = qkv + tok0*(3*D_) + 2*D_ + h*HD_;

    // ---- async load Q tile (128x64) + first K/V tile ----
    {
        #pragma unroll
        for (int j = 0; j < 4; j++){
            int ch = tid + j*256;            // 0..1023
            int r = ch >> 3, c = (ch & 7)*8;
            CP16(sptr(&Qs[r*QPAD + c]), Qg + (size_t)r*(3*D_) + c);
        }
        #pragma unroll
        for (int j = 0; j < 2; j++){
            int ch = tid + j*256;            // 0..511
            int r = ch >> 3, c = (ch & 7)*8;
            CP16(sptr(&Ks[0][r*QPAD + c]), Kg + (size_t)r*(3*D_) + c);
            CP16(sptr(&Vs[0][r*QPAD + c]), Vg + (size_t)r*(3*D_) + c);
        }
        CP_COMMIT();
    }

    // softmax state (per thread: rows g and g+8 of warp strip)
    float m0 = -1e30f, m1 = -1e30f, l0 = 0.f, l1 = 0.f;
    float o[8][4];
    #pragma unroll
    for (int i=0;i<8;i++){ o[i][0]=0.f; o[i][1]=0.f; o[i][2]=0.f; o[i][3]=0.f; }

    // ldmatrix addresses
    const uint32_t aQ = sptr(&Qs[(warp*16 + (lane & 15))*QPAD + (lane >> 4)*8]);
    uint32_t kA[4], vA[4];
    #pragma unroll
    for (int bt = 0; bt < 4; bt++)
        kA[bt] = sptr(&Ks[0][(bt*16 + ((lane>>4)&1)*8 + (lane&7))*QPAD
                             + ((lane>>3)&1)*8]);
    #pragma unroll
    for (int dt = 0; dt < 4; dt++)
        vA[dt] = sptr(&Vs[0][(((lane>>3)&1)*8 + (lane&7))*QPAD
                             + dt*16 + ((lane>>4)&1)*8]);
    const uint32_t KVS = 64*QPAD*2;   // stage stride bytes

    const int nkt = 2*qt + 2;
    int s = 0;
    for (int kt = 0; kt < nkt; kt++){
        if (kt + 1 < nkt){
            const bf16* Kg2 = Kg + (size_t)(kt+1)*64*(3*D_);
            const bf16* Vg2 = Vg + (size_t)(kt+1)*64*(3*D_);
            bf16* ksm = &Ks[s^1][0];
            bf16* vsm = &Vs[s^1][0];
            #pragma unroll
            for (int j = 0; j < 2; j++){
                int ch = tid + j*256;
                int r = ch >> 3, c = (ch & 7)*8;
                CP16(sptr(ksm + r*QPAD + c), Kg2 + (size_t)r*(3*D_) + c);
                CP16(sptr(vsm + r*QPAD + c), Vg2 + (size_t)r*(3*D_) + c);
            }
        }
        CP_COMMIT();
        CP_WAIT1();
        __syncthreads();

        const uint32_t so = s * KVS;

        // ---- S = Q @ K^T  (16 x 64 per warp) ----
        float sc[8][4];
        #pragma unroll
        for (int i=0;i<8;i++){ sc[i][0]=0.f; sc[i][1]=0.f; sc[i][2]=0.f; sc[i][3]=0.f; }
        #pragma unroll
        for (int kk = 0; kk < 4; kk++){
            uint32_t a0,a1,a2,a3;
            LDSM4(a0,a1,a2,a3, aQ + kk*32);
            uint32_t bb[4][4];
            #pragma unroll
            for (int bt = 0; bt < 4; bt++)
                LDSM4(bb[bt][0],bb[bt][1],bb[bt][2],bb[bt][3], kA[bt] + so + kk*32);
            #pragma unroll
            for (int nt = 0; nt < 8; nt++){
                const int bt = nt >> 1, su = (nt & 1)*2;
                MMA16816(sc[nt][0],sc[nt][1],sc[nt][2],sc[nt][3],
                         a0,a1,a2,a3, bb[bt][su], bb[bt][su+1]);
            }
        }

        // ---- scale + causal mask ----
        const int qrow0 = q0 + warp*16 + g;
        const int qrow1 = qrow0 + 8;
        const bool masked = (kt >= 2*qt);
        #pragma unroll
        for (int nt = 0; nt < 8; nt++){
            int col = kt*64 + nt*8 + 2*t;
            #pragma unroll
            for (int u = 0; u < 4; u++) sc[nt][u] *= 0.125f;
            if (masked){
                if (col   > qrow0) sc[nt][0] = -1e30f;
                if (col+1 > qrow0) sc[nt][1] = -1e30f;
                if (col   > qrow1) sc[nt][2] = -1e30f;
                if (col+1 > qrow1) sc[nt][3] = -1e30f;
            }
        }

        // ---- online softmax ----
        float tm0 = -1e30f, tm1 = -1e30f;
        #pragma unroll
        for (int nt = 0; nt < 8; nt++){
            tm0 = fmaxf(tm0, fmaxf(sc[nt][0], sc[nt][1]));
            tm1 = fmaxf(tm1, fmaxf(sc[nt][2], sc[nt][3]));
        }
        tm0 = fmaxf(tm0, __shfl_xor_sync(0xffffffffu, tm0, 1));
        tm0 = fmaxf(tm0, __shfl_xor_sync(0xffffffffu, tm0, 2));
        tm1 = fmaxf(tm1, __shfl_xor_sync(0xffffffffu, tm1, 1));
        tm1 = fmaxf(tm1, __shfl_xor_sync(0xffffffffu, tm1, 2));
        float nm0 = fmaxf(m0, tm0), nm1 = fmaxf(m1, tm1);
        float al0 = __expf(m0 - nm0), al1 = __expf(m1 - nm1);
        m0 = nm0; m1 = nm1;
        float ps0 = 0.f, ps1 = 0.f;
        #pragma unroll
        for (int nt = 0; nt < 8; nt++){
            sc[nt][0] = __expf(sc[nt][0] - nm0);
            sc[nt][1] = __expf(sc[nt][1] - nm0);
            sc[nt][2] = __expf(sc[nt][2] - nm1);
            sc[nt][3] = __expf(sc[nt][3] - nm1);
            ps0 += sc[nt][0] + sc[nt][1];
            ps1 += sc[nt][2] + sc[nt][3];
        }
        l0 = l0*al0 + ps0;
        l1 = l1*al1 + ps1;
        #pragma unroll
        for (int dt = 0; dt < 8; dt++){
            o[dt][0] *= al0; o[dt][1] *= al0;
            o[dt][2] *= al1; o[dt][3] *= al1;
        }

        // ---- P @ V ----
        #pragma unroll
        for (int kk = 0; kk < 4; kk++){
            uint32_t a0 = pk2(sc[2*kk][0],   sc[2*kk][1]);
            uint32_t a1 = pk2(sc[2*kk][2],   sc[2*kk][3]);
            uint32_t a2 = pk2(sc[2*kk+1][0], sc[2*kk+1][1]);
            uint32_t a3 = pk2(sc[2*kk+1][2], sc[2*kk+1][3]);
            uint32_t vv[4][4];
            #pragma unroll
            for (int dt = 0; dt < 4; dt++)
                LDSM4T(vv[dt][0],vv[dt][1],vv[dt][2],vv[dt][3],
                       vA[dt] + so + kk*16*QPAD*2);
            #pragma unroll
            for (int nt = 0; nt < 8; nt++){
                const int dt = nt >> 1, su = (nt & 1)*2;
                MMA16816(o[nt][0],o[nt][1],o[nt][2],o[nt][3],
                         a0,a1,a2,a3, vv[dt][su], vv[dt][su+1]);
            }
        }
        __syncthreads();
        s ^= 1;
    }

    // ---- finalize ----
    l0 += __shfl_xor_sync(0xffffffffu, l0, 1);
    l0 += __shfl_xor_sync(0xffffffffu, l0, 2);
    l1 += __shfl_xor_sync(0xffffffffu, l1, 1);
    l1 += __shfl_xor_sync(0xffffffffu, l1, 2);
    float r0 = 1.f/l0, r1 = 1.f/l1;
    const int row0 = q0 + warp*16 + g;
    bf16* O0 = out + (tok0 + row0)*D_ + h*HD_;
    bf16* O1 = out + (tok0 + row0 + 8)*D_ + h*HD_;
    #pragma unroll
    for (int dt = 0; dt < 8; dt++){
        int cc = dt*8 + 2*t;
        *(__nv_bfloat162*)&O0[cc] = __floats2bfloat162_rn(o[dt][0]*r0, o[dt][1]*r0);
        *(__nv_bfloat162*)&O1[cc] = __floats2bfloat162_rn(o[dt][2]*r1, o[dt][3]*r1);
    }
}

// ---------------- per-token NLL ----------------
__global__ void nll_kernel(const int* __restrict__ labels,
                           const float* __restrict__ logits,
                           float* __restrict__ nll){
    int t = blockIdx.x;
    int tid = threadIdx.x;
    int b = t >> 10, s = t & (S_-1);
    if (s == S_-1){ if (tid == 0) nll[t] = 0.f; return; }
    const float* row = logits + (size_t)t*V_;
    float m = -3.402823e38f, sum = 0.f;
    for (int i = tid; i < V_; i += 256){
        float v = row[i];
        float nm = fmaxf(m, v);
        sum = sum*expf(m - nm) + expf(v - nm);
        m = nm;
    }
    float M = block_reduce<true>(m);
    sum *= expf(m - M);
    float S = block_reduce<false>(sum);
    if (tid == 0){
        int tgt = labels[b*S_ + s + 1];
        nll[t] = logf(S) + M - row[tgt];
    }
}

// ---------------- final mean ----------------
__global__ void final_reduce(const float* __restrict__ nll, float* __restrict__ out){
    float s = 0.f;
    for (int t = threadIdx.x; t < N_; t += 256)
        if ((t & (S_-1)) != S_-1) s += nll[t];
    s = block_reduce<false>(s);
    if (threadIdx.x == 0) out[0] = s * (1.f/(B_*(S_-1)));
}

// ---------------- host launch ----------------
static inline int mgrid(size_t n){
    size_t n4 = n >> 2;
    size_t b = (n4 + 255) / 256;
    return (int)b;
}

extern "C" void kernel_launch(void* const* d_in, const int* in_sizes, int n_in,
                              void* d_out, int out_size){
    const int*   ids    = (const int*)  d_in[0];
    const int*   labels = (const int*)  d_in[1];
    const float* lam    = (const float*)d_in[2];
    const float* emb    = (const float*)d_in[3];
    const float* Wqkv   = (const float*)d_in[4];
    const float* Wo     = (const float*)d_in[5];
    const float* W1     = (const float*)d_in[6];
    const float* W2     = (const float*)d_in[7];
    const float* g1     = (const float*)d_in[8];
    const float* g2     = (const float*)d_in[9];
    const float* gf     = (const float*)d_in[10];
    const float* d_emb  = (const float*)d_in[11];
    const float* d_Wqkv = (const float*)d_in[12];
    const float* d_Wo   = (const float*)d_in[13];
    const float* d_W1   = (const float*)d_in[14];
    const float* d_W2   = (const float*)d_in[15];
    const float* d_g1   = (const float*)d_in[16];
    const float* d_g2   = (const float*)d_in[17];
    const float* d_gf   = (const float*)d_in[18];

    float *p_embm, *p_g1, *p_g2, *p_gf;
    bf16  *p_embh, *p_WqkvT, *p_WoT, *p_W1T, *p_W2T, *p_a, *p_o, *p_ff, *p_qkvh;
    float *p_x, *p_logits, *p_nll;
    cudaGetSymbolAddress((void**)&p_embm,   g_embm);
    cudaGetSymbolAddress((void**)&p_embh,   g_embh);
    cudaGetSymbolAddress((void**)&p_WqkvT,  g_WqkvT);
    cudaGetSymbolAddress((void**)&p_WoT,    g_WoT);
    cudaGetSymbolAddress((void**)&p_W1T,    g_W1T);
    cudaGetSymbolAddress((void**)&p_W2T,    g_W2T);
    cudaGetSymbolAddress((void**)&p_g1,     g_g1);
    cudaGetSymbolAddress((void**)&p_g2,     g_g2);
    cudaGetSymbolAddress((void**)&p_gf,     g_gfm);
    cudaGetSymbolAddress((void**)&p_x,      g_x);
    cudaGetSymbolAddress((void**)&p_a,      g_a);
    cudaGetSymbolAddress((void**)&p_qkvh,   g_qkvh);
    cudaGetSymbolAddress((void**)&p_o,      g_o);
    cudaGetSymbolAddress((void**)&p_ff,     g_ff);
    cudaGetSymbolAddress((void**)&p_logits, g_logits);
    cudaGetSymbolAddress((void**)&p_nll,    g_nll);

    // ---- merge weights ----
    size_t n;
    dim3 t328(32, 8);
    n = (size_t)V_*D_;
    merge_emb_kernel<<<mgrid(n),256>>>(emb, d_emb, lam, p_embm, p_embh, n);
    tmerge_kernel<<<dim3(3*D_/32, D_/32, L_), t328>>>(Wqkv, d_Wqkv, lam, p_WqkvT,
                     D_, 3*D_, (size_t)L_*D_*3*D_);
    tmerge_kernel<<<dim3(D_/32, D_/32, L_), t328>>>(Wo, d_Wo, lam, p_WoT,
                     D_, D_, (size_t)L_*D_*D_);
    tmerge_kernel<<<dim3(DFF_/32, D_/32, L_), t328>>>(W1, d_W1, lam, p_W1T,
                     D_, DFF_, (size_t)L_*D_*DFF_);
    tmerge_kernel<<<dim3(D_/32, DFF_/32, L_), t328>>>(W2, d_W2, lam, p_W2T,
                     DFF_, D_, (size_t)L_*DFF_*D_);
    n = (size_t)L_*D_;  merge_kernel<<<mgrid(n),256>>>(g1, d_g1, lam, p_g1, n);
    n = (size_t)L_*D_;  merge_kernel<<<mgrid(n),256>>>(g2, d_g2, lam, p_g2, n);
    n = (size_t)D_;     merge_kernel<<<mgrid(n),256>>>(gf, d_gf, lam, p_gf, n);

    // ---- embed ----
    gather_kernel<<<N_, 256>>>(ids, p_embm, p_x);

    for (int l = 0; l < L_; l++){
        // attn
        ln_kernel<<<N_,256>>>(p_x, p_g1 + l*D_, p_a);
        hgemm<0,0,1><<<dim3(N_/128, 3*D_/128), 256>>>(N_, 3*D_, D_, p_a,
                         p_WqkvT + (size_t)l*3*D_*D_, nullptr, p_qkvh);
        flash_attn<<<dim3(S_/128, B_*H_), 256>>>(p_qkvh, p_o);
        hgemm<0,1,0><<<dim3(N_/128, D_/128), 256>>>(N_, D_, D_, p_o,
                         p_WoT + (size_t)l*D_*D_, p_x, p_x);
        // ffn
        ln_kernel<<<N_,256>>>(p_x, p_g2 + l*D_, p_a);
        hgemm<1,0,1><<<dim3(N_/128, DFF_/128), 256>>>(N_, DFF_, D_, p_a,
                         p_W1T + (size_t)l*DFF_*D_, nullptr, p_ff);
        hgemm<0,1,0><<<dim3(N_/128, D_/128), 256>>>(N_, D_, DFF_, p_ff,
                         p_W2T + (size_t)l*D_*DFF_, p_x, p_x);
    }

    // ---- head ----
    ln_kernel<<<N_,256>>>(p_x, p_gf, p_a);
    hgemm<0,0,0><<<dim3(N_/128, V_/128), 256>>>(N_, V_, D_, p_a, p_embh,
                     nullptr, p_logits);
    nll_kernel<<<N_,256>>>(labels, p_logits, p_nll);
    final_reduce<<<1,256>>>(p_nll, (float*)d_out);
}

// round 8
// speedup vs baseline: 2.6601x; 1.0474x over previous
#include <cuda_runtime.h>
#include <cuda_bf16.h>
#include <math.h>
#include <stddef.h>
#include <stdint.h>

#define L_   2
#define D_   1024
#define H_   16
#define HD_  64
#define DFF_ 4096
#define V_   32000
#define B_   2
#define S_   1024
#define N_   (B_*S_)   // 2048 tokens

typedef __nv_bfloat16 bf16;

// ---------------- device scratch (static, no allocations) ----------------
__device__ float g_embm[(size_t)V_*D_];          // fp32 for gather
__device__ uint32_t g_embf8[(size_t)V_*D_/4];    // e4m3 x4 packed, scale 256
__device__ bf16  g_WqkvT[(size_t)L_*3*D_*D_];
__device__ bf16  g_WoT [(size_t)L_*D_*D_];
__device__ bf16  g_W1T [(size_t)L_*DFF_*D_];
__device__ bf16  g_W2T [(size_t)L_*D_*DFF_];
__device__ float g_g1  [L_*D_];
__device__ float g_g2  [L_*D_];
__device__ float g_gfm [D_];
__device__ float g_x   [(size_t)N_*D_];
__device__ bf16  g_a   [(size_t)N_*D_];          // LN output (bf16)
__device__ uint32_t g_af8[(size_t)N_*D_/4];      // final-LN e4m3 x4, scale 4
__device__ bf16  g_qkvh[(size_t)N_*3*D_];
__device__ bf16  g_o   [(size_t)N_*D_];
__device__ bf16  g_ff  [(size_t)N_*DFF_];
__device__ float2 g_part[(size_t)N_*256];        // [token][nblock] lse partials
__device__ float g_tgt [N_];
__device__ float g_nll [N_];

// ---------------- helpers ----------------
__device__ __forceinline__ float warp_sum(float v){
    #pragma unroll
    for (int o=16;o;o>>=1) v += __shfl_down_sync(0xffffffffu, v, o);
    return v;
}
__device__ __forceinline__ float warp_max(float v){
    #pragma unroll
    for (int o=16;o;o>>=1) v = fmaxf(v, __shfl_down_sync(0xffffffffu, v, o));
    return v;
}
template<bool MAXRED>
__device__ __forceinline__ float block_reduce(float v){
    __shared__ float sh[8];
    int tid = threadIdx.x;
    v = MAXRED ? warp_max(v) : warp_sum(v);
    __syncthreads();
    if ((tid & 31) == 0) sh[tid>>5] = v;
    __syncthreads();
    if (tid < 32){
        float a = (tid < 8) ? sh[tid] : (MAXRED ? -3.402823e38f : 0.f);
        a = MAXRED ? warp_max(a) : warp_sum(a);
        if (tid == 0) sh[0] = a;
    }
    __syncthreads();
    return sh[0];
}
__device__ __forceinline__ float gelu_f(float x){
    float x3 = x*x*x;
    return 0.5f*x*(1.f + tanhf(0.7978845608028654f*(x + 0.044715f*x3)));
}
__device__ __forceinline__ uint32_t sptr(const void* p){
    return (uint32_t)__cvta_generic_to_shared(p);
}
__device__ __forceinline__ uint32_t pk2(float lo, float hi){
    uint32_t r;
    asm("cvt.rn.bf16x2.f32 %0, %1, %2;" : "=r"(r) : "f"(hi), "f"(lo));
    return r;
}
// pack 4 floats -> 4 e4m3 bytes, byte0 = v0
__device__ __forceinline__ uint32_t pk4_e4m3(float v0, float v1, float v2, float v3){
    uint16_t h0, h1;
    asm("cvt.rn.satfinite.e4m3x2.f32 %0, %1, %2;" : "=h"(h0) : "f"(v1), "f"(v0));
    asm("cvt.rn.satfinite.e4m3x2.f32 %0, %1, %2;" : "=h"(h1) : "f"(v3), "f"(v2));
    return (uint32_t)h0 | ((uint32_t)h1 << 16);
}

#define CP16(dst, src) \
    asm volatile("cp.async.cg.shared.global [%0], [%1], 16;\n" :: "r"(dst), "l"(src))
#define CP_COMMIT()  asm volatile("cp.async.commit_group;\n" ::)
#define CP_WAIT1()   asm volatile("cp.async.wait_group 1;\n" ::)

#define LDSM4(r0,r1,r2,r3,addr) \
    asm volatile("ldmatrix.sync.aligned.m8n8.x4.shared.b16 {%0,%1,%2,%3}, [%4];" \
                 : "=r"(r0), "=r"(r1), "=r"(r2), "=r"(r3) : "r"(addr))
#define LDSM4T(r0,r1,r2,r3,addr) \
    asm volatile("ldmatrix.sync.aligned.m8n8.x4.trans.shared.b16 {%0,%1,%2,%3}, [%4];" \
                 : "=r"(r0), "=r"(r1), "=r"(r2), "=r"(r3) : "r"(addr))
#define MMA16816(c0,c1,c2,c3,a0,a1,a2,a3,b0,b1) \
    asm volatile( \
        "mma.sync.aligned.m16n8k16.row.col.f32.bf16.bf16.f32 " \
        "{%0,%1,%2,%3}, {%4,%5,%6,%7}, {%8,%9}, {%0,%1,%2,%3};\n" \
        : "+f"(c0), "+f"(c1), "+f"(c2), "+f"(c3) \
        : "r"(a0), "r"(a1), "r"(a2), "r"(a3), "r"(b0), "r"(b1))
#define MMAF8(c0,c1,c2,c3,a0,a1,a2,a3,b0,b1) \
    asm volatile( \
        "mma.sync.aligned.m16n8k32.row.col.f32.e4m3.e4m3.f32 " \
        "{%0,%1,%2,%3}, {%4,%5,%6,%7}, {%8,%9}, {%0,%1,%2,%3};\n" \
        : "+f"(c0), "+f"(c1), "+f"(c2), "+f"(c3) \
        : "r"(a0), "r"(a1), "r"(a2), "r"(a3), "r"(b0), "r"(b1))

// ---------------- merge kernels ----------------
__global__ void merge_kernel(const float* __restrict__ base,
                             const float* __restrict__ delta,
                             const float* __restrict__ lam,
                             float* __restrict__ out, size_t n){
    size_t n4 = n >> 2;
    float l0 = lam[0], l1 = lam[1];
    const float4* b4 = (const float4*)base;
    const float4* d0 = (const float4*)delta;
    const float4* d1 = (const float4*)(delta + n);
    float4* o4 = (float4*)out;
    for (size_t i = (size_t)blockIdx.x*blockDim.x + threadIdx.x; i < n4;
         i += (size_t)gridDim.x*blockDim.x){
        float4 b = b4[i], x0 = d0[i], x1 = d1[i], r;
        r.x = b.x + l0*x0.x + l1*x1.x;
        r.y = b.y + l0*x0.y + l1*x1.y;
        r.z = b.z + l0*x0.z + l1*x1.z;
        r.w = b.w + l0*x0.w + l1*x1.w;
        o4[i] = r;
    }
}
// emb merge: fp32 out (gather) + e4m3 out (logits GEMM, scale 256)
__global__ void merge_emb_kernel(const float* __restrict__ base,
                                 const float* __restrict__ delta,
                                 const float* __restrict__ lam,
                                 float* __restrict__ outf,
                                 uint32_t* __restrict__ outf8, size_t n){
    size_t n4 = n >> 2;
    float l0 = lam[0], l1 = lam[1];
    const float4* b4 = (const float4*)base;
    const float4* d0 = (const float4*)delta;
    const float4* d1 = (const float4*)(delta + n);
    float4* o4 = (float4*)outf;
    for (size_t i = (size_t)blockIdx.x*blockDim.x + threadIdx.x; i < n4;
         i += (size_t)gridDim.x*blockDim.x){
        float4 b = b4[i], x0 = d0[i], x1 = d1[i], r;
        r.x = b.x + l0*x0.x + l1*x1.x;
        r.y = b.y + l0*x0.y + l1*x1.y;
        r.z = b.z + l0*x0.z + l1*x1.z;
        r.w = b.w + l0*x0.w + l1*x1.w;
        o4[i] = r;
        outf8[i] = pk4_e4m3(r.x*256.f, r.y*256.f, r.z*256.f, r.w*256.f);
    }
}
__global__ void tmerge_kernel(const float* __restrict__ base,
                              const float* __restrict__ delta,
                              const float* __restrict__ lam,
                              bf16* __restrict__ out,
                              int K, int Nw, size_t tstride){
    __shared__ float tile[32][33];
    int z = blockIdx.z;
    size_t mo = (size_t)z*K*Nw;
    float l0 = lam[0], l1 = lam[1];
    int n0 = blockIdx.x*32, k0 = blockIdx.y*32;
    #pragma unroll
    for (int j = 0; j < 32; j += 8){
        int k = k0 + threadIdx.y + j;
        int nn = n0 + threadIdx.x;
        size_t idx = mo + (size_t)k*Nw + nn;
        tile[threadIdx.y + j][threadIdx.x] =
            base[idx] + l0*delta[idx] + l1*delta[tstride + idx];
    }
    __syncthreads();
    #pragma unroll
    for (int j = 0; j < 32; j += 8){
        int nn = n0 + threadIdx.y + j;
        int k = k0 + threadIdx.x;
        out[mo + (size_t)nn*K + k] = __float2bfloat16(tile[threadIdx.x][threadIdx.y + j]);
    }
}

// ---------------- gather / layernorm ----------------
__global__ void gather_kernel(const int* __restrict__ ids,
                              const float* __restrict__ embm,
                              float* __restrict__ x){
    int t = blockIdx.x;
    int id = ids[t];
    const float4* src = (const float4*)(embm + (size_t)id*D_);
    float4* dst = (float4*)(x + (size_t)t*D_);
    for (int d = threadIdx.x; d < D_/4; d += blockDim.x) dst[d] = src[d];
}
__global__ void ln_kernel(const float* __restrict__ x,
                          const float* __restrict__ g,
                          bf16* __restrict__ out){
    int t = blockIdx.x;
    int tid = threadIdx.x;
    const float* xr = x + (size_t)t*D_;
    float s = 0.f, ss = 0.f;
    for (int d = tid; d < D_; d += 256){ float v = xr[d]; s += v; ss = fmaf(v, v, ss); }
    float tots = block_reduce<false>(s);
    float totss = block_reduce<false>(ss);
    float mu = tots * (1.f/D_);
    float var = totss * (1.f/D_) - mu*mu;
    float inv = rsqrtf(var + 1e-5f);
    bf16* orow = out + (size_t)t*D_;
    for (int d = tid; d < D_; d += 256)
        orow[d] = __float2bfloat16((xr[d]-mu)*inv*g[d]);
}
// final LN -> e4m3 packed, scale 4
__global__ void ln_f8_kernel(const float* __restrict__ x,
                             const float* __restrict__ g,
                             uint32_t* __restrict__ out){
    int t = blockIdx.x;
    int tid = threadIdx.x;
    const float* xr = x + (size_t)t*D_;
    float s = 0.f, ss = 0.f;
    for (int d = tid; d < D_; d += 256){ float v = xr[d]; s += v; ss = fmaf(v, v, ss); }
    float tots = block_reduce<false>(s);
    float totss = block_reduce<false>(ss);
    float mu = tots * (1.f/D_);
    float var = totss * (1.f/D_) - mu*mu;
    float inv = rsqrtf(var + 1e-5f);
    int d = tid*4;
    float v0 = (xr[d]-mu)*inv*g[d]     * 4.f;
    float v1 = (xr[d+1]-mu)*inv*g[d+1] * 4.f;
    float v2 = (xr[d+2]-mu)*inv*g[d+2] * 4.f;
    float v3 = (xr[d+3]-mu)*inv*g[d+3] * 4.f;
    out[(size_t)t*(D_/4) + tid] = pk4_e4m3(v0, v1, v2, v3);
}

// ================= bf16 GEMM (NT, cp.async + ldmatrix) ====================
#define PAD 40

template<int ACT, int RES, int OUTBF>
__global__ void __launch_bounds__(256) hgemm(int M, int N, int K,
                        const bf16* __restrict__ A,
                        const bf16* __restrict__ Bt,
                        const float* __restrict__ Res,
                        void* __restrict__ Cout){
    __shared__ __align__(16) bf16 As[2][128*PAD];
    __shared__ __align__(16) bf16 Bs[2][128*PAD];

    const int tid  = threadIdx.x;
    const int lane = tid & 31;
    const int warp = tid >> 5;
    const int g    = lane >> 2;
    const int t    = lane & 3;
    const int wm   = warp >> 1;
    const int wn   = warp & 1;
    const int row0 = blockIdx.x * 128;
    const int col0 = blockIdx.y * 128;

    float c[2][8][4];
    #pragma unroll
    for (int i=0;i<2;i++)
        #pragma unroll
        for (int j=0;j<8;j++)
            #pragma unroll
            for (int k=0;k<4;k++) c[i][j][k]=0.f;

    const int r1 = tid >> 2;
    const int c8 = (tid & 3) * 8;
    const bf16* Ag0 = A  + (size_t)(row0 + r1)*K + c8;
    const bf16* Ag1 = A  + (size_t)(row0 + r1 + 64)*K + c8;
    const bf16* Bg0 = Bt + (size_t)(col0 + r1)*K + c8;
    const bf16* Bg1 = Bt + (size_t)(col0 + r1 + 64)*K + c8;
    const uint32_t sa0 = sptr(&As[0][r1*PAD + c8]);
    const uint32_t sa1 = sptr(&As[0][(r1+64)*PAD + c8]);
    const uint32_t sb0 = sptr(&Bs[0][r1*PAD + c8]);
    const uint32_t sb1 = sptr(&Bs[0][(r1+64)*PAD + c8]);
    const uint32_t SS = 128*PAD*2;

    uint32_t aAddr[2];
    #pragma unroll
    for (int mt = 0; mt < 2; mt++)
        aAddr[mt] = sptr(&As[0][(wm*32 + mt*16 + (lane & 15))*PAD + (lane >> 4)*8]);
    uint32_t bAddr[4];
    #pragma unroll
    for (int bt = 0; bt < 4; bt++)
        bAddr[bt] = sptr(&Bs[0][(wn*64 + bt*16 + ((lane>>4)&1)*8 + (lane&7))*PAD
                                + ((lane>>3)&1)*8]);

    {
        CP16(sa0, Ag0); CP16(sa1, Ag1);
        CP16(sb0, Bg0); CP16(sb1, Bg1);
        CP_COMMIT();
    }

    const int KT = K >> 5;
    int s = 0;
    for (int kt = 0; kt < KT; kt++){
        if (kt + 1 < KT){
            const int ko = (kt + 1) << 5;
            const uint32_t so = (s ^ 1) * SS;
            CP16(sa0 + so, Ag0 + ko); CP16(sa1 + so, Ag1 + ko);
            CP16(sb0 + so, Bg0 + ko); CP16(sb1 + so, Bg1 + ko);
        }
        CP_COMMIT();
        CP_WAIT1();
        __syncthreads();

        const uint32_t sb = s * SS;
        #pragma unroll
        for (int ks = 0; ks < 2; ks++){
            const uint32_t kb = sb + ks*32;
            uint32_t a[2][4];
            #pragma unroll
            for (int mt = 0; mt < 2; mt++)
                LDSM4(a[mt][0], a[mt][1], a[mt][2], a[mt][3], aAddr[mt] + kb);
            uint32_t bb[4][4];
            #pragma unroll
            for (int bt = 0; bt < 4; bt++)
                LDSM4(bb[bt][0], bb[bt][1], bb[bt][2], bb[bt][3], bAddr[bt] + kb);
            #pragma unroll
            for (int mt = 0; mt < 2; mt++)
                #pragma unroll
                for (int nt = 0; nt < 8; nt++){
                    const int bt = nt >> 1, su = (nt & 1) * 2;
                    MMA16816(c[mt][nt][0], c[mt][nt][1], c[mt][nt][2], c[mt][nt][3],
                             a[mt][0], a[mt][1], a[mt][2], a[mt][3],
                             bb[bt][su], bb[bt][su+1]);
                }
        }
        __syncthreads();
        s ^= 1;
    }

    float* Cf = (float*)Cout;
    bf16*  Ch = (bf16*)Cout;
    #pragma unroll
    for (int mt = 0; mt < 2; mt++){
        int r0 = row0 + wm*32 + mt*16 + g;
        #pragma unroll
        for (int nt = 0; nt < 8; nt++){
            int cc = col0 + wn*64 + nt*8 + 2*t;
            float v0 = c[mt][nt][0], v1 = c[mt][nt][1];
            float v2 = c[mt][nt][2], v3 = c[mt][nt][3];
            if (RES){
                v0 += Res[(size_t)r0*N + cc];
                v1 += Res[(size_t)r0*N + cc + 1];
                v2 += Res[(size_t)(r0+8)*N + cc];
                v3 += Res[(size_t)(r0+8)*N + cc + 1];
            }
            if (ACT){
                v0 = gelu_f(v0); v1 = gelu_f(v1);
                v2 = gelu_f(v2); v3 = gelu_f(v3);
            }
            if (OUTBF){
                *(__nv_bfloat162*)&Ch[(size_t)r0*N + cc]     = __floats2bfloat162_rn(v0, v1);
                *(__nv_bfloat162*)&Ch[(size_t)(r0+8)*N + cc] = __floats2bfloat162_rn(v2, v3);
            } else {
                Cf[(size_t)r0*N + cc]         = v0;
                Cf[(size_t)r0*N + cc + 1]     = v1;
                Cf[(size_t)(r0+8)*N + cc]     = v2;
                Cf[(size_t)(r0+8)*N + cc + 1] = v3;
            }
        }
    }
}

// ============ FP8 logits GEMM with fused logsumexp epilogue ===============
// A, Bt are e4m3 packed as u16 pairs (K16 = K/2 u16 units = 512).
// logits = acc / 1024 (a scaled x4, emb x256). No C output: per-token
// (max, sumexp) partial over this CTA's 128 cols + target logit.
__global__ void __launch_bounds__(256) f8gemm_lse(int K16,
                        const bf16* __restrict__ A,
                        const bf16* __restrict__ Bt,
                        const int* __restrict__ labels,
                        float2* __restrict__ part,
                        float* __restrict__ tgtlog){
    __shared__ __align__(16) bf16 As[2][128*PAD];
    __shared__ __align__(16) bf16 Bs[2][128*PAD];
    __shared__ float2 red[2][128];
    __shared__ float  tgv[2][128];
    __shared__ float  tgf[2][128];

    const int tid  = threadIdx.x;
    const int lane = tid & 31;
    const int warp = tid >> 5;
    const int g    = lane >> 2;
    const int t    = lane & 3;
    const int wm   = warp >> 1;
    const int wn   = warp & 1;
    const int row0 = blockIdx.x * 128;
    const int col0 = blockIdx.y * 128;
    const int K = K16;

    float c[2][8][4];
    #pragma unroll
    for (int i=0;i<2;i++)
        #pragma unroll
        for (int j=0;j<8;j++)
            #pragma unroll
            for (int k=0;k<4;k++) c[i][j][k]=0.f;

    const int r1 = tid >> 2;
    const int c8 = (tid & 3) * 8;
    const bf16* Ag0 = A  + (size_t)(row0 + r1)*K + c8;
    const bf16* Ag1 = A  + (size_t)(row0 + r1 + 64)*K + c8;
    const bf16* Bg0 = Bt + (size_t)(col0 + r1)*K + c8;
    const bf16* Bg1 = Bt + (size_t)(col0 + r1 + 64)*K + c8;
    const uint32_t sa0 = sptr(&As[0][r1*PAD + c8]);
    const uint32_t sa1 = sptr(&As[0][(r1+64)*PAD + c8]);
    const uint32_t sb0 = sptr(&Bs[0][r1*PAD + c8]);
    const uint32_t sb1 = sptr(&Bs[0][(r1+64)*PAD + c8]);
    const uint32_t SS = 128*PAD*2;

    uint32_t aAddr[2];
    #pragma unroll
    for (int mt = 0; mt < 2; mt++)
        aAddr[mt] = sptr(&As[0][(wm*32 + mt*16 + (lane & 15))*PAD + (lane >> 4)*8]);
    uint32_t bAddr[4];
    #pragma unroll
    for (int bt = 0; bt < 4; bt++)
        bAddr[bt] = sptr(&Bs[0][(wn*64 + bt*16 + ((lane>>4)&1)*8 + (lane&7))*PAD
                                + ((lane>>3)&1)*8]);

    {
        CP16(sa0, Ag0); CP16(sa1, Ag1);
        CP16(sb0, Bg0); CP16(sb1, Bg1);
        CP_COMMIT();
    }

    const int KT = K >> 5;
    int s = 0;
    for (int kt = 0; kt < KT; kt++){
        if (kt + 1 < KT){
            const int ko = (kt + 1) << 5;
            const uint32_t so = (s ^ 1) * SS;
            CP16(sa0 + so, Ag0 + ko); CP16(sa1 + so, Ag1 + ko);
            CP16(sb0 + so, Bg0 + ko); CP16(sb1 + so, Bg1 + ko);
        }
        CP_COMMIT();
        CP_WAIT1();
        __syncthreads();

        const uint32_t sb = s * SS;
        #pragma unroll
        for (int ks = 0; ks < 2; ks++){
            const uint32_t kb = sb + ks*32;
            uint32_t a[2][4];
            #pragma unroll
            for (int mt = 0; mt < 2; mt++)
                LDSM4(a[mt][0], a[mt][1], a[mt][2], a[mt][3], aAddr[mt] + kb);
            uint32_t bb[4][4];
            #pragma unroll
            for (int bt = 0; bt < 4; bt++)
                LDSM4(bb[bt][0], bb[bt][1], bb[bt][2], bb[bt][3], bAddr[bt] + kb);
            #pragma unroll
            for (int mt = 0; mt < 2; mt++)
                #pragma unroll
                for (int nt = 0; nt < 8; nt++){
                    const int bt = nt >> 1, su = (nt & 1) * 2;
                    MMAF8(c[mt][nt][0], c[mt][nt][1], c[mt][nt][2], c[mt][nt][3],
                          a[mt][0], a[mt][1], a[mt][2], a[mt][3],
                          bb[bt][su], bb[bt][su+1]);
                }
        }
        __syncthreads();
        s ^= 1;
    }

    // ---- fused LSE epilogue ----
    const float scale = 1.f/1024.f;
    #pragma unroll
    for (int mt = 0; mt < 2; mt++){
        #pragma unroll
        for (int half = 0; half < 2; half++){
            const int rowi = wm*32 + mt*16 + half*8 + g;
            const int token = row0 + rowi;
            const int ss2 = token & (S_-1);
            const int tgt = (ss2 == S_-1) ? -1
                          : labels[(token >> 10)*S_ + ss2 + 1];
            float rm = -1e30f;
            float v[16];
            #pragma unroll
            for (int nt = 0; nt < 8; nt++){
                v[2*nt]   = c[mt][nt][2*half]   * scale;
                v[2*nt+1] = c[mt][nt][2*half+1] * scale;
                rm = fmaxf(rm, fmaxf(v[2*nt], v[2*nt+1]));
            }
            float rs = 0.f, tv = 0.f, tf = 0.f;
            #pragma unroll
            for (int nt = 0; nt < 8; nt++){
                rs += __expf(v[2*nt] - rm) + __expf(v[2*nt+1] - rm);
                int col = col0 + wn*64 + nt*8 + 2*t;
                if (col   == tgt){ tv = v[2*nt];   tf = 1.f; }
                if (col+1 == tgt){ tv = v[2*nt+1]; tf = 1.f; }
            }
            // quad reduce over t (lanes xor 1, 2)
            #pragma unroll
            for (int o = 1; o <= 2; o <<= 1){
                float om = __shfl_xor_sync(0xffffffffu, rm, o);
                float os = __shfl_xor_sync(0xffffffffu, rs, o);
                float nm = fmaxf(rm, om);
                rs = rs*__expf(rm - nm) + os*__expf(om - nm);
                rm = nm;
                tv += __shfl_xor_sync(0xffffffffu, tv, o);
                tf += __shfl_xor_sync(0xffffffffu, tf, o);
            }
            if (t == 0){
                red[wn][rowi] = make_float2(rm, rs);
                tgv[wn][rowi] = tv;
                tgf[wn][rowi] = tf;
            }
        }
    }
    __syncthreads();
    if (tid < 128){
        float2 p0 = red[0][tid], p1 = red[1][tid];
        float m = fmaxf(p0.x, p1.x);
        float sm = p0.y*__expf(p0.x - m) + p1.y*__expf(p1.x - m);
        int token = row0 + tid;
        part[(size_t)token*256 + blockIdx.y] = make_float2(m, sm);
        if (tgf[0][tid] + tgf[1][tid] > 0.5f)
            tgtlog[token] = tgv[0][tid] + tgv[1][tid];
    }
}

// ================= fused flash attention ==================================
#define QPAD 72

__global__ void __launch_bounds__(256) flash_attn(const bf16* __restrict__ qkv,
                                                  bf16* __restrict__ out){
    __shared__ __align__(16) bf16 Qs[128*QPAD];
    __shared__ __align__(16) bf16 Ks[2][64*QPAD];
    __shared__ __align__(16) bf16 Vs[2][64*QPAD];

    const int tid  = threadIdx.x;
    const int lane = tid & 31;
    const int warp = tid >> 5;
    const int g    = lane >> 2;
    const int t    = lane & 3;
    const int qt   = blockIdx.x;
    const int bh   = blockIdx.y;
    const int b    = bh >> 4, h = bh & 15;
    const int q0   = qt * 128;

    const size_t tok0 = (size_t)b * S_;
    const bf16* Qg = qkv + (tok0 + q0)*(3*D_) + h*HD_;
    const bf16* Kg = qkv + tok0*(3*D_) + D_   + h*HD_;
    const bf16* Vg = qkv + tok0*(3*D_) + 2*D_ + h*HD_;

    {
        #pragma unroll
        for (int j = 0; j < 4; j++){
            int ch = tid + j*256;
            int r = ch >> 3, c = (ch & 7)*8;
            CP16(sptr(&Qs[r*QPAD + c]), Qg + (size_t)r*(3*D_) + c);
        }
        #pragma unroll
        for (int j = 0; j < 2; j++){
            int ch = tid + j*256;
            int r = ch >> 3, c = (ch & 7)*8;
            CP16(sptr(&Ks[0][r*QPAD + c]), Kg + (size_t)r*(3*D_) + c);
            CP16(sptr(&Vs[0][r*QPAD + c]), Vg + (size_t)r*(3*D_) + c);
        }
        CP_COMMIT();
    }

    float m0 = -1e30f, m1 = -1e30f, l0 = 0.f, l1 = 0.f;
    float o[8][4];
    #pragma unroll
    for (int i=0;i<8;i++){ o[i][0]=0.f; o[i][1]=0.f; o[i][2]=0.f; o[i][3]=0.f; }

    const uint32_t aQ = sptr(&Qs[(warp*16 + (lane & 15))*QPAD + (lane >> 4)*8]);
    uint32_t kA[4], vA[4];
    #pragma unroll
    for (int bt = 0; bt < 4; bt++)
        kA[bt] = sptr(&Ks[0][(bt*16 + ((lane>>4)&1)*8 + (lane&7))*QPAD
                             + ((lane>>3)&1)*8]);
    #pragma unroll
    for (int dt = 0; dt < 4; dt++)
        vA[dt] = sptr(&Vs[0][(((lane>>3)&1)*8 + (lane&7))*QPAD
                             + dt*16 + ((lane>>4)&1)*8]);
    const uint32_t KVS = 64*QPAD*2;

    const int nkt = 2*qt + 2;
    int s = 0;
    for (int kt = 0; kt < nkt; kt++){
        if (kt + 1 < nkt){
            const bf16* Kg2 = Kg + (size_t)(kt+1)*64*(3*D_);
            const bf16* Vg2 = Vg + (size_t)(kt+1)*64*(3*D_);
            bf16* ksm = &Ks[s^1][0];
            bf16* vsm = &Vs[s^1][0];
            #pragma unroll
            for (int j = 0; j < 2; j++){
                int ch = tid + j*256;
                int r = ch >> 3, c = (ch & 7)*8;
                CP16(sptr(ksm + r*QPAD + c), Kg2 + (size_t)r*(3*D_) + c);
                CP16(sptr(vsm + r*QPAD + c), Vg2 + (size_t)r*(3*D_) + c);
            }
        }
        CP_COMMIT();
        CP_WAIT1();
        __syncthreads();

        const uint32_t so = s * KVS;

        float sc[8][4];
        #pragma unroll
        for (int i=0;i<8;i++){ sc[i][0]=0.f; sc[i][1]=0.f; sc[i][2]=0.f; sc[i][3]=0.f; }
        #pragma unroll
        for (int kk = 0; kk < 4; kk++){
            uint32_t a0,a1,a2,a3;
            LDSM4(a0,a1,a2,a3, aQ + kk*32);
            uint32_t bb[4][4];
            #pragma unroll
            for (int bt = 0; bt < 4; bt++)
                LDSM4(bb[bt][0],bb[bt][1],bb[bt][2],bb[bt][3], kA[bt] + so + kk*32);
            #pragma unroll
            for (int nt = 0; nt < 8; nt++){
                const int bt = nt >> 1, su = (nt & 1)*2;
                MMA16816(sc[nt][0],sc[nt][1],sc[nt][2],sc[nt][3],
                         a0,a1,a2,a3, bb[bt][su], bb[bt][su+1]);
            }
        }

        const int qrow0 = q0 + warp*16 + g;
        const int qrow1 = qrow0 + 8;
        const bool masked = (kt >= 2*qt);
        #pragma unroll
        for (int nt = 0; nt < 8; nt++){
            int col = kt*64 + nt*8 + 2*t;
            #pragma unroll
            for (int u = 0; u < 4; u++) sc[nt][u] *= 0.125f;
            if (masked){
                if (col   > qrow0) sc[nt][0] = -1e30f;
                if (col+1 > qrow0) sc[nt][1] = -1e30f;
                if (col   > qrow1) sc[nt][2] = -1e30f;
                if (col+1 > qrow1) sc[nt][3] = -1e30f;
            }
        }

        float tm0 = -1e30f, tm1 = -1e30f;
        #pragma unroll
        for (int nt = 0; nt < 8; nt++){
            tm0 = fmaxf(tm0, fmaxf(sc[nt][0], sc[nt][1]));
            tm1 = fmaxf(tm1, fmaxf(sc[nt][2], sc[nt][3]));
        }
        tm0 = fmaxf(tm0, __shfl_xor_sync(0xffffffffu, tm0, 1));
        tm0 = fmaxf(tm0, __shfl_xor_sync(0xffffffffu, tm0, 2));
        tm1 = fmaxf(tm1, __shfl_xor_sync(0xffffffffu, tm1, 1));
        tm1 = fmaxf(tm1, __shfl_xor_sync(0xffffffffu, tm1, 2));
        float nm0 = fmaxf(m0, tm0), nm1 = fmaxf(m1, tm1);
        float al0 = __expf(m0 - nm0), al1 = __expf(m1 - nm1);
        m0 = nm0; m1 = nm1;
        float ps0 = 0.f, ps1 = 0.f;
        #pragma unroll
        for (int nt = 0; nt < 8; nt++){
            sc[nt][0] = __expf(sc[nt][0] - nm0);
            sc[nt][1] = __expf(sc[nt][1] - nm0);
            sc[nt][2] = __expf(sc[nt][2] - nm1);
            sc[nt][3] = __expf(sc[nt][3] - nm1);
            ps0 += sc[nt][0] + sc[nt][1];
            ps1 += sc[nt][2] + sc[nt][3];
        }
        l0 = l0*al0 + ps0;
        l1 = l1*al1 + ps1;
        #pragma unroll
        for (int dt = 0; dt < 8; dt++){
            o[dt][0] *= al0; o[dt][1] *= al0;
            o[dt][2] *= al1; o[dt][3] *= al1;
        }

        #pragma unroll
        for (int kk = 0; kk < 4; kk++){
            uint32_t a0 = pk2(sc[2*kk][0],   sc[2*kk][1]);
            uint32_t a1 = pk2(sc[2*kk][2],   sc[2*kk][3]);
            uint32_t a2 = pk2(sc[2*kk+1][0], sc[2*kk+1][1]);
            uint32_t a3 = pk2(sc[2*kk+1][2], sc[2*kk+1][3]);
            uint32_t vv[4][4];
            #pragma unroll
            for (int dt = 0; dt < 4; dt++)
                LDSM4T(vv[dt][0],vv[dt][1],vv[dt][2],vv[dt][3],
                       vA[dt] + so + kk*16*QPAD*2);
            #pragma unroll
            for (int nt = 0; nt < 8; nt++){
                const int dt = nt >> 1, su = (nt & 1)*2;
                MMA16816(o[nt][0],o[nt][1],o[nt][2],o[nt][3],
                         a0,a1,a2,a3, vv[dt][su], vv[dt][su+1]);
            }
        }
        __syncthreads();
        s ^= 1;
    }

    l0 += __shfl_xor_sync(0xffffffffu, l0, 1);
    l0 += __shfl_xor_sync(0xffffffffu, l0, 2);
    l1 += __shfl_xor_sync(0xffffffffu, l1, 1);
    l1 += __shfl_xor_sync(0xffffffffu, l1, 2);
    float r0 = 1.f/l0, r1 = 1.f/l1;
    const int row0 = q0 + warp*16 + g;
    bf16* O0 = out + (tok0 + row0)*D_ + h*HD_;
    bf16* O1 = out + (tok0 + row0 + 8)*D_ + h*HD_;
    #pragma unroll
    for (int dt = 0; dt < 8; dt++){
        int cc = dt*8 + 2*t;
        *(__nv_bfloat162*)&O0[cc] = __floats2bfloat162_rn(o[dt][0]*r0, o[dt][1]*r0);
        *(__nv_bfloat162*)&O1[cc] = __floats2bfloat162_rn(o[dt][2]*r1, o[dt][3]*r1);
    }
}

// ---------------- NLL final: combine 250 logsumexp partials ----------------
__global__ void nll_final(const float2* __restrict__ part,
                          const float* __restrict__ tgtlog,
                          float* __restrict__ nll){
    int t = blockIdx.x, tid = threadIdx.x;
    int ss = t & (S_-1);
    if (ss == S_-1){ if (tid == 0) nll[t] = 0.f; return; }
    float2 p = (tid < V_/128) ? part[(size_t)t*256 + tid]
                              : make_float2(-1e30f, 0.f);
    float M = block_reduce<true>(p.x);
    float S = block_reduce<false>(p.y * __expf(p.x - M));
    if (tid == 0) nll[t] = logf(S) + M - tgtlog[t];
}

// ---------------- final mean ----------------
__global__ void final_reduce(const float* __restrict__ nll, float* __restrict__ out){
    float s = 0.f;
    for (int t = threadIdx.x; t < N_; t += 256)
        if ((t & (S_-1)) != S_-1) s += nll[t];
    s = block_reduce<false>(s);
    if (threadIdx.x == 0) out[0] = s * (1.f/(B_*(S_-1)));
}

// ---------------- host launch ----------------
static inline int mgrid(size_t n){
    size_t n4 = n >> 2;
    return (int)((n4 + 255) / 256);
}

extern "C" void kernel_launch(void* const* d_in, const int* in_sizes, int n_in,
                              void* d_out, int out_size){
    const int*   ids    = (const int*)  d_in[0];
    const int*   labels = (const int*)  d_in[1];
    const float* lam    = (const float*)d_in[2];
    const float* emb    = (const float*)d_in[3];
    const float* Wqkv   = (const float*)d_in[4];
    const float* Wo     = (const float*)d_in[5];
    const float* W1     = (const float*)d_in[6];
    const float* W2     = (const float*)d_in[7];
    const float* g1     = (const float*)d_in[8];
    const float* g2     = (const float*)d_in[9];
    const float* gf     = (const float*)d_in[10];
    const float* d_emb  = (const float*)d_in[11];
    const float* d_Wqkv = (const float*)d_in[12];
    const float* d_Wo   = (const float*)d_in[13];
    const float* d_W1   = (const float*)d_in[14];
    const float* d_W2   = (const float*)d_in[15];
    const float* d_g1   = (const float*)d_in[16];
    const float* d_g2   = (const float*)d_in[17];
    const float* d_gf   = (const float*)d_in[18];

    float *p_embm, *p_g1, *p_g2, *p_gf, *p_x, *p_tgt, *p_nll;
    bf16  *p_WqkvT, *p_WoT, *p_W1T, *p_W2T, *p_a, *p_o, *p_ff, *p_qkvh;
    uint32_t *p_embf8, *p_af8;
    float2 *p_part;
    cudaGetSymbolAddress((void**)&p_embm,   g_embm);
    cudaGetSymbolAddress((void**)&p_embf8,  g_embf8);
    cudaGetSymbolAddress((void**)&p_WqkvT,  g_WqkvT);
    cudaGetSymbolAddress((void**)&p_WoT,    g_WoT);
    cudaGetSymbolAddress((void**)&p_W1T,    g_W1T);
    cudaGetSymbolAddress((void**)&p_W2T,    g_W2T);
    cudaGetSymbolAddress((void**)&p_g1,     g_g1);
    cudaGetSymbolAddress((void**)&p_g2,     g_g2);
    cudaGetSymbolAddress((void**)&p_gf,     g_gfm);
    cudaGetSymbolAddress((void**)&p_x,      g_x);
    cudaGetSymbolAddress((void**)&p_a,      g_a);
    cudaGetSymbolAddress((void**)&p_af8,    g_af8);
    cudaGetSymbolAddress((void**)&p_qkvh,   g_qkvh);
    cudaGetSymbolAddress((void**)&p_o,      g_o);
    cudaGetSymbolAddress((void**)&p_ff,     g_ff);
    cudaGetSymbolAddress((void**)&p_part,   g_part);
    cudaGetSymbolAddress((void**)&p_tgt,    g_tgt);
    cudaGetSymbolAddress((void**)&p_nll,    g_nll);

    // ---- merge weights ----
    size_t n;
    dim3 t328(32, 8);
    n = (size_t)V_*D_;
    merge_emb_kernel<<<mgrid(n),256>>>(emb, d_emb, lam, p_embm, p_embf8, n);
    tmerge_kernel<<<dim3(3*D_/32, D_/32, L_), t328>>>(Wqkv, d_Wqkv, lam, p_WqkvT,
                     D_, 3*D_, (size_t)L_*D_*3*D_);
    tmerge_kernel<<<dim3(D_/32, D_/32, L_), t328>>>(Wo, d_Wo, lam, p_WoT,
                     D_, D_, (size_t)L_*D_*D_);
    tmerge_kernel<<<dim3(DFF_/32, D_/32, L_), t328>>>(W1, d_W1, lam, p_W1T,
                     D_, DFF_, (size_t)L_*D_*DFF_);
    tmerge_kernel<<<dim3(D_/32, DFF_/32, L_), t328>>>(W2, d_W2, lam, p_W2T,
                     DFF_, D_, (size_t)L_*DFF_*D_);
    n = (size_t)L_*D_;  merge_kernel<<<mgrid(n),256>>>(g1, d_g1, lam, p_g1, n);
    n = (size_t)L_*D_;  merge_kernel<<<mgrid(n),256>>>(g2, d_g2, lam, p_g2, n);
    n = (size_t)D_;     merge_kernel<<<mgrid(n),256>>>(gf, d_gf, lam, p_gf, n);

    // ---- embed ----
    gather_kernel<<<N_, 256>>>(ids, p_embm, p_x);

    for (int l = 0; l < L_; l++){
        ln_kernel<<<N_,256>>>(p_x, p_g1 + l*D_, p_a);
        hgemm<0,0,1><<<dim3(N_/128, 3*D_/128), 256>>>(N_, 3*D_, D_, p_a,
                         p_WqkvT + (size_t)l*3*D_*D_, nullptr, p_qkvh);
        flash_attn<<<dim3(S_/128, B_*H_), 256>>>(p_qkvh, p_o);
        hgemm<0,1,0><<<dim3(N_/128, D_/128), 256>>>(N_, D_, D_, p_o,
                         p_WoT + (size_t)l*D_*D_, p_x, p_x);
        ln_kernel<<<N_,256>>>(p_x, p_g2 + l*D_, p_a);
        hgemm<1,0,1><<<dim3(N_/128, DFF_/128), 256>>>(N_, DFF_, D_, p_a,
                         p_W1T + (size_t)l*DFF_*D_, nullptr, p_ff);
        hgemm<0,1,0><<<dim3(N_/128, D_/128), 256>>>(N_, D_, DFF_, p_ff,
                         p_W2T + (size_t)l*D_*DFF_, p_x, p_x);
    }

    // ---- head: fp8 logits GEMM with fused logsumexp ----
    ln_f8_kernel<<<N_,256>>>(p_x, p_gf, p_af8);
    f8gemm_lse<<<dim3(N_/128, V_/128), 256>>>(D_/2,
        (const bf16*)p_af8, (const bf16*)p_embf8, labels, p_part, p_tgt);
    nll_final<<<N_,256>>>(p_part, p_tgt, p_nll);
    final_reduce<<<1,256>>>(p_nll, (float*)d_out);
}